// round 14
// baseline (speedup 1.0000x reference)
#include <cuda_runtime.h>
#include <cuda_fp16.h>
#include <math.h>
#include <stdint.h>

#define NMAX 100000
#define EMAX 3200000
#define RREL 15
#define NLAY 4
#define NB16 (NMAX * 16)

__device__ __half g_xr[(size_t)RREL * NMAX * 32];
__device__ float g_x0[NMAX * 36];
__device__ float g_x[NMAX * 32];
__device__ float g_h[NMAX * 32];
__device__ float g_hp[NMAX * 32];
__device__ float g_sp[NMAX];
__device__ float g_qv[NMAX * 16];
__device__ float g_kv[NMAX * 16];
__device__ int   g_rowptr[NMAX + 1];
__device__ int   g_cursor16[NB16];
__device__ int   g_count16[NB16];
__device__ int   g_rp16[NB16];
__device__ int   g_epack[EMAX];
__device__ int   g_bsum[6400];
__device__ int   g_boff[6400];
__device__ double g_stats[NLAY][2];
__device__ double g_pool[32];
__device__ double g_psum[3];
__device__ double g_M[6];
__device__ unsigned int g_mnkey[3], g_mxkey[3];
__device__ float  g_pmean[3];
__device__ float g_V[9];
__device__ float g_pscale;
__device__ double g_fstats[2];
__device__ float  g_fp[2];

__device__ __forceinline__ double warpSumD(double v) {
    for (int o = 16; o > 0; o >>= 1) v += __shfl_down_sync(0xffffffffu, v, o);
    return v;
}
__device__ __forceinline__ float warpSumF(float v) {
    for (int o = 16; o > 0; o >>= 1) v += __shfl_xor_sync(0xffffffffu, v, o);
    return v;
}
__device__ __forceinline__ unsigned int fkey(float f) {
    unsigned int u = __float_as_uint(f);
    return (u & 0x80000000u) ? ~u : (u | 0x80000000u);
}
__device__ __forceinline__ float funkey(unsigned int k) {
    return (k & 0x80000000u) ? __uint_as_float(k ^ 0x80000000u) : __uint_as_float(~k);
}

__device__ __forceinline__ void mma16816(float& d0, float& d1, float& d2, float& d3,
    uint32_t a0, uint32_t a1, uint32_t a2, uint32_t a3, uint32_t b0, uint32_t b1) {
    asm volatile("mma.sync.aligned.m16n8k16.row.col.f32.f16.f16.f32 "
        "{%0,%1,%2,%3}, {%4,%5,%6,%7}, {%8,%9}, {%0,%1,%2,%3};"
        : "+f"(d0), "+f"(d1), "+f"(d2), "+f"(d3)
        : "r"(a0), "r"(a1), "r"(a2), "r"(a3), "r"(b0), "r"(b1));
}

__global__ void k_zero() {
    int i = blockIdx.x * blockDim.x + threadIdx.x;
    int stride = gridDim.x * blockDim.x;
    for (int j = i; j < NB16; j += stride) g_count16[j] = 0;
    if (i == 0) {
        for (int l = 0; l < NLAY; l++) { g_stats[l][0] = 0.0; g_stats[l][1] = 0.0; }
        for (int o = 0; o < 32; o++) g_pool[o] = 0.0;
        for (int c = 0; c < 3; c++) { g_psum[c] = 0.0; g_mnkey[c] = 0xFFFFFFFFu; g_mxkey[c] = 0u; }
        for (int c = 0; c < 6; c++) g_M[c] = 0.0;
        g_fstats[0] = 0.0; g_fstats[1] = 0.0;
    }
}

__global__ void k_stats(const float* __restrict__ d, int n) {
    int gtid = blockIdx.x * blockDim.x + threadIdx.x;
    int stride = gridDim.x * blockDim.x;
    double s0 = 0, s1 = 0, s2 = 0;
    double r00 = 0, r01 = 0, r02 = 0, r11 = 0, r12 = 0, r22 = 0;
    float mn0 = 3e38f, mn1 = 3e38f, mn2 = 3e38f;
    float mx0 = -3e38f, mx1 = -3e38f, mx2 = -3e38f;
    for (int i = gtid; i < n; i += stride) {
        float x = d[i * 35 + 0], y = d[i * 35 + 1], z = d[i * 35 + 2];
        double dx = x, dy = y, dz = z;
        s0 += dx; s1 += dy; s2 += dz;
        r00 += dx * dx; r01 += dx * dy; r02 += dx * dz;
        r11 += dy * dy; r12 += dy * dz; r22 += dz * dz;
        mn0 = fminf(mn0, x); mx0 = fmaxf(mx0, x);
        mn1 = fminf(mn1, y); mx1 = fmaxf(mx1, y);
        mn2 = fminf(mn2, z); mx2 = fmaxf(mx2, z);
    }
    double fs = 0, fss = 0;
    int total = n * 35;
    int q4 = total >> 2;
    const float4* d4 = (const float4*)d;
    for (int j = gtid; j < q4; j += stride) {
        float4 v = d4[j];
        int idx = j * 4;
        int c = idx - (idx / 35) * 35;
        if (c >= 3) { double t = v.x; fs += t; fss += t * t; }
        c = (c == 34) ? 0 : c + 1;
        if (c >= 3) { double t = v.y; fs += t; fss += t * t; }
        c = (c == 34) ? 0 : c + 1;
        if (c >= 3) { double t = v.z; fs += t; fss += t * t; }
        c = (c == 34) ? 0 : c + 1;
        if (c >= 3) { double t = v.w; fs += t; fss += t * t; }
    }
    if (gtid == 0) {
        for (int idx = q4 * 4; idx < total; idx++) {
            int c = idx - (idx / 35) * 35;
            if (c >= 3) { double t = d[idx]; fs += t; fss += t * t; }
        }
    }
    s0 = warpSumD(s0); s1 = warpSumD(s1); s2 = warpSumD(s2);
    r00 = warpSumD(r00); r01 = warpSumD(r01); r02 = warpSumD(r02);
    r11 = warpSumD(r11); r12 = warpSumD(r12); r22 = warpSumD(r22);
    fs = warpSumD(fs); fss = warpSumD(fss);
    for (int o = 16; o > 0; o >>= 1) {
        mn0 = fminf(mn0, __shfl_down_sync(0xffffffffu, mn0, o));
        mn1 = fminf(mn1, __shfl_down_sync(0xffffffffu, mn1, o));
        mn2 = fminf(mn2, __shfl_down_sync(0xffffffffu, mn2, o));
        mx0 = fmaxf(mx0, __shfl_down_sync(0xffffffffu, mx0, o));
        mx1 = fmaxf(mx1, __shfl_down_sync(0xffffffffu, mx1, o));
        mx2 = fmaxf(mx2, __shfl_down_sync(0xffffffffu, mx2, o));
    }
    if ((threadIdx.x & 31) == 0) {
        atomicAdd(&g_psum[0], s0); atomicAdd(&g_psum[1], s1); atomicAdd(&g_psum[2], s2);
        atomicAdd(&g_M[0], r00); atomicAdd(&g_M[1], r01); atomicAdd(&g_M[2], r02);
        atomicAdd(&g_M[3], r11); atomicAdd(&g_M[4], r12); atomicAdd(&g_M[5], r22);
        atomicAdd(&g_fstats[0], fs); atomicAdd(&g_fstats[1], fss);
        atomicMin(&g_mnkey[0], fkey(mn0)); atomicMax(&g_mxkey[0], fkey(mx0));
        atomicMin(&g_mnkey[1], fkey(mn1)); atomicMax(&g_mxkey[1], fkey(mx1));
        atomicMin(&g_mnkey[2], fkey(mn2)); atomicMax(&g_mxkey[2], fkey(mx2));
    }
}

// ---- LAPACK dsyevd path (PASSING convention): dsytd2('L') -> dsteqr('I') -> V=Q*Z ----
__device__ void dev_dlartg(double f, double g, double* cs, double* sn, double* r) {
    if (g == 0.0) { *cs = 1.0; *sn = 0.0; *r = f; }
    else if (f == 0.0) { *cs = 0.0; *sn = 1.0; *r = g; }
    else {
        double rr = sqrt(f * f + g * g);
        double c = f / rr, s = g / rr;
        if (fabs(f) > fabs(g) && c < 0.0) { c = -c; s = -s; rr = -rr; }
        *cs = c; *sn = s; *r = rr;
    }
}

__device__ void dev_dlaev2(double a, double b, double c,
                           double* rt1, double* rt2, double* cs1, double* sn1) {
    double sm = a + c, df = a - c;
    double adf = fabs(df), tb = b + b, ab = fabs(tb);
    double acmx, acmn;
    if (fabs(a) > fabs(c)) { acmx = a; acmn = c; } else { acmx = c; acmn = a; }
    double rt;
    if (adf > ab) rt = adf * sqrt(1.0 + (ab / adf) * (ab / adf));
    else if (adf < ab) rt = ab * sqrt(1.0 + (adf / ab) * (adf / ab));
    else rt = ab * sqrt(2.0);
    int sgn1;
    if (sm < 0.0) { *rt1 = 0.5 * (sm - rt); sgn1 = -1; *rt2 = (acmx / *rt1) * acmn - (b / *rt1) * b; }
    else if (sm > 0.0) { *rt1 = 0.5 * (sm + rt); sgn1 = 1; *rt2 = (acmx / *rt1) * acmn - (b / *rt1) * b; }
    else { *rt1 = 0.5 * rt; *rt2 = -0.5 * rt; sgn1 = 1; }
    double cs; int sgn2;
    if (df >= 0.0) { cs = df + rt; sgn2 = 1; } else { cs = df - rt; sgn2 = -1; }
    double acs = fabs(cs);
    if (acs > ab) {
        double ct = -tb / cs;
        *sn1 = 1.0 / sqrt(1.0 + ct * ct);
        *cs1 = ct * (*sn1);
    } else {
        if (ab == 0.0) { *cs1 = 1.0; *sn1 = 0.0; }
        else {
            double tn = -cs / tb;
            *cs1 = 1.0 / sqrt(1.0 + tn * tn);
            *sn1 = tn * (*cs1);
        }
    }
    if (sgn1 == sgn2) { double tn = *cs1; *cs1 = -(*sn1); *sn1 = tn; }
}

__global__ void k_eigh(int nn) {
    if (threadIdx.x != 0) return;
    double mu0 = g_psum[0] / (double)nn, mu1 = g_psum[1] / (double)nn, mu2 = g_psum[2] / (double)nn;
    g_pmean[0] = (float)mu0; g_pmean[1] = (float)mu1; g_pmean[2] = (float)mu2;
    {
        double cnt = (double)nn * 32.0;
        double mu = g_fstats[0] / cnt;
        double var = g_fstats[1] / cnt - mu * mu;
        if (var < 0.0) var = 0.0;
        g_fp[0] = (float)mu;
        g_fp[1] = (float)sqrt(var) + 1e-5f;
    }
    double mus[3] = {mu0, mu1, mu2};
    float mxab = 0.f;
    for (int c = 0; c < 3; c++) {
        float hi = funkey(g_mxkey[c]) - (float)mus[c];
        float lo = (float)mus[c] - funkey(g_mnkey[c]);
        mxab = fmaxf(mxab, fmaxf(hi, lo));
    }
    float sc = (1.0f / mxab) * 0.999999f;
    g_pscale = sc;
    double s2 = (double)sc * (double)sc;
    double N = (double)nn;
    double a00 = (g_M[0] - N * mu0 * mu0) * s2;
    double a01 = (g_M[1] - N * mu0 * mu1) * s2;
    double a02 = (g_M[2] - N * mu0 * mu2) * s2;
    double a11 = (g_M[3] - N * mu1 * mu1) * s2;
    double a12 = (g_M[4] - N * mu1 * mu2) * s2;
    double a22 = (g_M[5] - N * mu2 * mu2) * s2;

    double d[4], e[3];
    double tau = 0.0, v1 = 0.0;
    {
        double alpha = a01;
        double x = a02;
        double xnorm = fabs(x);
        double beta;
        if (xnorm == 0.0) { tau = 0.0; beta = alpha; }
        else {
            double hy = sqrt(alpha * alpha + xnorm * xnorm);
            beta = (alpha >= 0.0) ? -hy : hy;
            tau = (beta - alpha) / beta;
            v1 = x / (alpha - beta);
        }
        e[1] = beta;
        double nd11 = a11, nd12 = a12, nd22 = a22;
        if (tau != 0.0) {
            double w0 = tau * (a11 + a12 * v1);
            double w1 = tau * (a12 + a22 * v1);
            double al = -0.5 * tau * (w0 + w1 * v1);
            w0 += al;
            w1 += al * v1;
            nd11 = a11 - 2.0 * w0;
            nd12 = a12 - (w1 + w0 * v1);
            nd22 = a22 - 2.0 * v1 * w1;
        }
        d[1] = a00; d[2] = nd11; d[3] = nd22;
        e[2] = nd12;
    }

    const int n = 3;
    double Z[4][4];
    for (int i = 1; i <= 3; i++)
        for (int j = 1; j <= 3; j++) Z[i][j] = (i == j) ? 1.0 : 0.0;
    double eps = 2.220446049250313e-16;
    double eps2 = eps * eps;
    double safmin = 2.2250738585072014e-308;
    int nmaxit = n * 30, jtot = 0;
    double wc[4], ws[4];
    int l1 = 1;
    while (true) {
        if (l1 > n) break;
        if (l1 > 1) e[l1 - 1] = 0.0;
        int m;
        if (l1 <= n - 1) {
            for (m = l1; m <= n - 1; m++) {
                double tst = fabs(e[m]);
                if (tst == 0.0) break;
                if (tst <= (sqrt(fabs(d[m])) * sqrt(fabs(d[m + 1]))) * eps) { e[m] = 0.0; break; }
            }
        } else m = n;
        int l = l1, lend = m;
        l1 = m + 1;
        if (lend == l) continue;
        if (fabs(d[lend]) < fabs(d[l])) { int t = lend; lend = l; l = t; }
        if (lend > l) {
            while (true) {
                int mm;
                if (l != lend) {
                    for (mm = l; mm <= lend - 1; mm++) {
                        double tst = e[mm] * e[mm];
                        if (tst <= (eps2 * fabs(d[mm]) * fabs(d[mm + 1]) + safmin)) break;
                    }
                } else mm = lend;
                m = mm;
                if (m < lend) e[m] = 0.0;
                double p = d[l];
                if (m == l) { d[l] = p; l = l + 1; if (l <= lend) continue; else break; }
                if (m == l + 1) {
                    double rt1, rt2, c, s;
                    dev_dlaev2(d[l], e[l], d[l + 1], &rt1, &rt2, &c, &s);
                    for (int i = 1; i <= n; i++) {
                        double temp = Z[i][l + 1];
                        Z[i][l + 1] = c * temp - s * Z[i][l];
                        Z[i][l] = s * temp + c * Z[i][l];
                    }
                    d[l] = rt1; d[l + 1] = rt2; e[l] = 0.0;
                    l = l + 2;
                    if (l <= lend) continue; else break;
                }
                if (jtot == nmaxit) break;
                jtot++;
                double g = (d[l + 1] - p) / (2.0 * e[l]);
                double r = sqrt(g * g + 1.0);
                double sg = (g >= 0.0) ? fabs(r) : -fabs(r);
                g = d[m] - p + e[l] / (g + sg);
                double s = 1.0, c = 1.0;
                p = 0.0;
                for (int i = m - 1; i >= l; i--) {
                    double f = s * e[i];
                    double b = c * e[i];
                    dev_dlartg(g, f, &c, &s, &r);
                    if (i != m - 1) e[i + 1] = r;
                    g = d[i + 1] - p;
                    r = (d[i] - g) * s + 2.0 * c * b;
                    p = s * r;
                    d[i + 1] = g + p;
                    g = c * r - b;
                    wc[i] = c; ws[i] = -s;
                }
                for (int j = m - 1; j >= l; j--) {
                    double cj = wc[j], sj = ws[j];
                    for (int i = 1; i <= n; i++) {
                        double temp = Z[i][j + 1];
                        Z[i][j + 1] = cj * temp - sj * Z[i][j];
                        Z[i][j] = sj * temp + cj * Z[i][j];
                    }
                }
                d[l] = d[l] - p;
                e[l] = g;
            }
        } else {
            while (true) {
                int mm;
                if (l != lend) {
                    for (mm = l; mm >= lend + 1; mm--) {
                        double tst = e[mm - 1] * e[mm - 1];
                        if (tst <= (eps2 * fabs(d[mm]) * fabs(d[mm - 1]) + safmin)) break;
                    }
                } else mm = lend;
                m = mm;
                if (m > lend) e[m - 1] = 0.0;
                double p = d[l];
                if (m == l) { d[l] = p; l = l - 1; if (l >= lend) continue; else break; }
                if (m == l - 1) {
                    double rt1, rt2, c, s;
                    dev_dlaev2(d[l - 1], e[l - 1], d[l], &rt1, &rt2, &c, &s);
                    for (int i = 1; i <= n; i++) {
                        double temp = Z[i][l];
                        Z[i][l] = c * temp - s * Z[i][l - 1];
                        Z[i][l - 1] = s * temp + c * Z[i][l - 1];
                    }
                    d[l - 1] = rt1; d[l] = rt2; e[l - 1] = 0.0;
                    l = l - 2;
                    if (l >= lend) continue; else break;
                }
                if (jtot == nmaxit) break;
                jtot++;
                double g = (d[l - 1] - p) / (2.0 * e[l - 1]);
                double r = sqrt(g * g + 1.0);
                double sg = (g >= 0.0) ? fabs(r) : -fabs(r);
                g = d[m] - p + e[l - 1] / (g + sg);
                double s = 1.0, c = 1.0;
                p = 0.0;
                for (int i = m; i <= l - 1; i++) {
                    double f = s * e[i];
                    double b = c * e[i];
                    dev_dlartg(g, f, &c, &s, &r);
                    if (i != m) e[i - 1] = r;
                    g = d[i] - p;
                    r = (d[i + 1] - g) * s + 2.0 * c * b;
                    p = s * r;
                    d[i] = g + p;
                    g = c * r - b;
                    wc[i] = c; ws[i] = s;
                }
                for (int j = m; j <= l - 1; j++) {
                    double cj = wc[j], sj = ws[j];
                    for (int i = 1; i <= n; i++) {
                        double temp = Z[i][j + 1];
                        Z[i][j + 1] = cj * temp - sj * Z[i][j];
                        Z[i][j] = sj * temp + cj * Z[i][j];
                    }
                }
                d[l] = d[l] - p;
                e[l - 1] = g;
            }
        }
    }
    for (int ii = 2; ii <= n; ii++) {
        int i = ii - 1, k = i;
        double p = d[i];
        for (int j = ii; j <= n; j++) if (d[j] < p) { k = j; p = d[j]; }
        if (k != i) {
            d[k] = d[i]; d[i] = p;
            for (int rr = 1; rr <= n; rr++) { double t = Z[rr][i]; Z[rr][i] = Z[rr][k]; Z[rr][k] = t; }
        }
    }
    double Q[4][4];
    Q[1][1] = 1.0; Q[1][2] = 0.0; Q[1][3] = 0.0;
    Q[2][1] = 0.0; Q[3][1] = 0.0;
    Q[2][2] = 1.0 - tau;
    Q[2][3] = -tau * v1;
    Q[3][2] = -tau * v1;
    Q[3][3] = 1.0 - tau * v1 * v1;
    for (int i = 1; i <= 3; i++)
        for (int j = 1; j <= 3; j++) {
            double acc = 0.0;
            for (int k = 1; k <= 3; k++) acc += Q[i][k] * Z[k][j];
            g_V[(i - 1) * 3 + (j - 1)] = (float)acc;
        }
}

__global__ void k_buildx0(const float* __restrict__ d, const float* __restrict__ ln1w,
                          const float* __restrict__ ln1b, int n) {
    int idx = blockIdx.x * blockDim.x + threadIdx.x;
    if (idx >= n * 36) return;
    int node = idx / 36, j = idx % 36;
    float val;
    if (j < 3) {
        float sc = g_pscale;
        float a = (d[node * 35 + 0] - g_pmean[0]) * sc;
        float b = (d[node * 35 + 1] - g_pmean[1]) * sc;
        float c = (d[node * 35 + 2] - g_pmean[2]) * sc;
        val = a * g_V[0 + j] + b * g_V[3 + j] + c * g_V[6 + j];
    } else if (j < 35) {
        val = (d[node * 35 + j] - g_fp[0]) / g_fp[1] * ln1w[j - 3] + ln1b[j - 3];
    } else val = 0.f;
    g_x0[idx] = val;
}

__global__ void k_hist(const int* __restrict__ ei, const int* __restrict__ et, int e) {
    int i = blockIdx.x * blockDim.x + threadIdx.x;
    if (i < e) atomicAdd(&g_count16[ei[e + i] * 16 + et[i]], 1);
}

__global__ void k_scanA(int ntot) {
    __shared__ int ws[8];
    int b = blockIdx.x, tid = threadIdx.x, lane = tid & 31, w = tid >> 5;
    int i = b * 256 + tid;
    int v = (i < ntot) ? g_count16[i] : 0;
    int x = v;
    for (int o = 1; o < 32; o <<= 1) {
        int y = __shfl_up_sync(0xffffffffu, x, o);
        if (lane >= o) x += y;
    }
    if (lane == 31) ws[w] = x;
    __syncthreads();
    if (tid == 0) {
        int run = 0;
        for (int j = 0; j < 8; j++) { int t = ws[j]; ws[j] = run; run += t; }
    }
    __syncthreads();
    int excl = x - v + ws[w];
    if (i < ntot) g_rp16[i] = excl;
    if (tid == 255) g_bsum[b] = excl + v;
}

__global__ void k_scanB(int nb) {
    __shared__ int sd[512];
    __shared__ int s_carry;
    int tid = threadIdx.x;
    if (tid == 0) s_carry = 0;
    __syncthreads();
    for (int b0 = 0; b0 < nb; b0 += 512) {
        int i = b0 + tid;
        int v = (i < nb) ? g_bsum[i] : 0;
        sd[tid] = v;
        __syncthreads();
        for (int o = 1; o < 512; o <<= 1) {
            int tv = (tid >= o) ? sd[tid - o] : 0;
            __syncthreads();
            sd[tid] += tv;
            __syncthreads();
        }
        int c = s_carry;
        if (i < nb) g_boff[i] = c + sd[tid] - v;
        __syncthreads();
        if (tid == 511) s_carry = c + sd[511];
        __syncthreads();
    }
}

__global__ void k_scanC(int ntot, int n, int e) {
    int i = blockIdx.x * blockDim.x + threadIdx.x;
    if (i >= ntot) return;
    int rp = g_rp16[i] + g_boff[i >> 8];
    g_rp16[i] = rp;
    g_cursor16[i] = rp;
    if ((i & 15) == 0) g_rowptr[i >> 4] = rp;
    if (i == 0) g_rowptr[n] = e;
}

__global__ void k_scatter(const int* __restrict__ ei, const int* __restrict__ et, int e) {
    int i = blockIdx.x * blockDim.x + threadIdx.x;
    if (i >= e) return;
    int r = et[i];
    int pos = atomicAdd(&g_cursor16[ei[e + i] * 16 + r], 1);
    g_epack[pos] = ei[i] | (r << 20);
}

// Tensor-core GEMM: xr[r] = x @ W[r] (fp16 in, fp32 acc), qv/kv fused epilogue.
template <int F, int STRIDE, int KP>
__global__ void k_gemm(const float* __restrict__ W, const float* __restrict__ qvec,
                       const float* __restrict__ kvec, int n) {
    __shared__ __half xs[128][56];
    __shared__ __half wt[32][56];
    __shared__ __half xout[128][36];
    __shared__ float sq[32], sk[32];
    int tid = threadIdx.x;
    int w = tid >> 5, lane = tid & 31, g = lane >> 2, t = lane & 3;
    int base = blockIdx.x * 128;
    const float* xbuf = (F == 35) ? g_x0 : g_x;

    for (int idx = tid; idx < 128 * KP; idx += 128) {
        int nl = idx / KP, f = idx % KP;
        int node = base + nl;
        float v = (f < F && node < n) ? xbuf[(size_t)node * STRIDE + f] : 0.f;
        xs[nl][f] = __float2half(v);
    }
    if (tid < 32) { sq[tid] = qvec[tid]; sk[tid] = kvec[tid]; }

    for (int r = 0; r < RREL; r++) {
        __syncthreads();
        for (int idx = tid; idx < 32 * KP; idx += 128) {
            int o = idx / KP, f = idx % KP;
            wt[o][f] = (f < F) ? __float2half(W[((size_t)r * F + f) * 32 + o]) : __float2half(0.f);
        }
        __syncthreads();
        for (int mt = 0; mt < 2; mt++) {
            int rowbase = w * 32 + mt * 16;
            float qp0 = 0, qp1 = 0, kp0 = 0, kp1 = 0;
            for (int nt = 0; nt < 4; nt++) {
                float d0 = 0, d1 = 0, d2 = 0, d3 = 0;
                #pragma unroll
                for (int ks = 0; ks < KP / 16; ks++) {
                    uint32_t a0 = *(const uint32_t*)&xs[rowbase + g][2 * t + ks * 16];
                    uint32_t a1 = *(const uint32_t*)&xs[rowbase + g + 8][2 * t + ks * 16];
                    uint32_t a2 = *(const uint32_t*)&xs[rowbase + g][2 * t + 8 + ks * 16];
                    uint32_t a3 = *(const uint32_t*)&xs[rowbase + g + 8][2 * t + 8 + ks * 16];
                    uint32_t b0 = *(const uint32_t*)&wt[nt * 8 + g][2 * t + ks * 16];
                    uint32_t b1 = *(const uint32_t*)&wt[nt * 8 + g][2 * t + 8 + ks * 16];
                    mma16816(d0, d1, d2, d3, a0, a1, a2, a3, b0, b1);
                }
                int c = nt * 8 + 2 * t;
                *(__half2*)&xout[rowbase + g][c] = __floats2half2_rn(d0, d1);
                *(__half2*)&xout[rowbase + g + 8][c] = __floats2half2_rn(d2, d3);
                qp0 += d0 * sq[c] + d1 * sq[c + 1];
                qp1 += d2 * sq[c] + d3 * sq[c + 1];
                kp0 += d0 * sk[c] + d1 * sk[c + 1];
                kp1 += d2 * sk[c] + d3 * sk[c + 1];
            }
            qp0 += __shfl_xor_sync(0xffffffffu, qp0, 1); qp0 += __shfl_xor_sync(0xffffffffu, qp0, 2);
            qp1 += __shfl_xor_sync(0xffffffffu, qp1, 1); qp1 += __shfl_xor_sync(0xffffffffu, qp1, 2);
            kp0 += __shfl_xor_sync(0xffffffffu, kp0, 1); kp0 += __shfl_xor_sync(0xffffffffu, kp0, 2);
            kp1 += __shfl_xor_sync(0xffffffffu, kp1, 1); kp1 += __shfl_xor_sync(0xffffffffu, kp1, 2);
            if (t == 0) {
                int n0 = base + rowbase + g, n1 = n0 + 8;
                if (n0 < n) { g_qv[n0 * 16 + r] = qp0; g_kv[n0 * 16 + r] = kp0; }
                if (n1 < n) { g_qv[n1 * 16 + r] = qp1; g_kv[n1 * 16 + r] = kp1; }
            }
        }
        __syncwarp();
        #pragma unroll
        for (int i = 0; i < 16; i++) {
            int rl = w * 32 + 2 * i + (lane >> 4);
            int node = base + rl;
            if (node < n) {
                uint32_t v = *(const uint32_t*)&xout[rl][(lane & 15) * 2];
                *(uint32_t*)&g_xr[((size_t)r * n + node) * 32 + (lane & 15) * 2] = v;
            }
        }
    }
}

// Phase A: relations [0,8) -> unnormalized partials (hp, sp). R11 loop body.
__global__ void k_edgeA(int n) {
    int warp = threadIdx.x >> 5, lane = threadIdx.x & 31;
    int node = blockIdx.x * 8 + warp;
    if (node >= n) return;
    __shared__ float sh_qv[8][16];
    __shared__ float sh_h[8][32];
    if (lane < 16) sh_qv[warp][lane] = g_qv[node * 16 + lane];
    __syncwarp();
    int beg = g_rowptr[node], end = g_rp16[node * 16 + 8];
    int fq = lane & 3, eg = lane >> 2;
    float s = 0.f;
    float acc[8];
    #pragma unroll
    for (int j = 0; j < 8; j++) acc[j] = 0.f;
    for (int cb = beg; cb < end; cb += 32) {
        int i = cb + lane;
        float ee = 0.f;
        int ofs = 0;
        if (i < end) {
            int p = g_epack[i];
            int r = p >> 20, src = p & 0xFFFFF;
            float a = sh_qv[warp][r] + g_kv[src * 16 + r];
            a = (a > 0.f) ? a : 0.2f * a;
            ee = __expf(a);
            ofs = (r * n + src) * 32;
        }
        s += ee;
        int cnt = min(32, end - cb);
        for (int jb = 0; jb < cnt; jb += 8) {
            int sl = jb + eg;
            float pw = __shfl_sync(0xffffffffu, ee, sl & 31);
            int of = __shfl_sync(0xffffffffu, ofs, sl & 31);
            if (sl >= cnt) pw = 0.f;
            uint4 v = *(const uint4*)&g_xr[(size_t)of + fq * 8];
            float2 f0 = __half22float2(*(__half2*)&v.x);
            float2 f1 = __half22float2(*(__half2*)&v.y);
            float2 f2 = __half22float2(*(__half2*)&v.z);
            float2 f3 = __half22float2(*(__half2*)&v.w);
            acc[0] += pw * f0.x; acc[1] += pw * f0.y;
            acc[2] += pw * f1.x; acc[3] += pw * f1.y;
            acc[4] += pw * f2.x; acc[5] += pw * f2.y;
            acc[6] += pw * f3.x; acc[7] += pw * f3.y;
        }
    }
    s = warpSumF(s);
    #pragma unroll
    for (int j = 0; j < 8; j++) {
        acc[j] += __shfl_xor_sync(0xffffffffu, acc[j], 4);
        acc[j] += __shfl_xor_sync(0xffffffffu, acc[j], 8);
        acc[j] += __shfl_xor_sync(0xffffffffu, acc[j], 16);
    }
    if (eg == 0) {
        #pragma unroll
        for (int j = 0; j < 8; j++) sh_h[warp][fq * 8 + j] = acc[j];
    }
    __syncwarp();
    g_hp[(size_t)node * 32 + lane] = sh_h[warp][lane];
    if (lane == 0) g_sp[node] = s;
}

// Phase B: relations [8,15) -> combine with phase A, normalize, bias+res, LN stats.
__global__ void k_edgeB(const float* __restrict__ bias, int layer, int n) {
    int warp = threadIdx.x >> 5, lane = threadIdx.x & 31;
    int node = blockIdx.x * 8 + warp;
    float h = 0.f;
    bool active = node < n;
    __shared__ float sh_qv[8][16];
    __shared__ float sh_h[8][32];
    if (active && lane < 16) sh_qv[warp][lane] = g_qv[node * 16 + lane];
    __syncwarp();
    if (active) {
        int begAll = g_rowptr[node];
        int beg = g_rp16[node * 16 + 8], end = g_rowptr[node + 1];
        float res = (layer > 0) ? g_x[(size_t)node * 32 + lane] : 0.f;
        if (end > begAll) {
            int fq = lane & 3, eg = lane >> 2;
            float s = 0.f;
            float acc[8];
            #pragma unroll
            for (int j = 0; j < 8; j++) acc[j] = 0.f;
            for (int cb = beg; cb < end; cb += 32) {
                int i = cb + lane;
                float ee = 0.f;
                int ofs = 0;
                if (i < end) {
                    int p = g_epack[i];
                    int r = p >> 20, src = p & 0xFFFFF;
                    float a = sh_qv[warp][r] + g_kv[src * 16 + r];
                    a = (a > 0.f) ? a : 0.2f * a;
                    ee = __expf(a);
                    ofs = (r * n + src) * 32;
                }
                s += ee;
                int cnt = min(32, end - cb);
                for (int jb = 0; jb < cnt; jb += 8) {
                    int sl = jb + eg;
                    float pw = __shfl_sync(0xffffffffu, ee, sl & 31);
                    int of = __shfl_sync(0xffffffffu, ofs, sl & 31);
                    if (sl >= cnt) pw = 0.f;
                    uint4 v = *(const uint4*)&g_xr[(size_t)of + fq * 8];
                    float2 f0 = __half22float2(*(__half2*)&v.x);
                    float2 f1 = __half22float2(*(__half2*)&v.y);
                    float2 f2 = __half22float2(*(__half2*)&v.z);
                    float2 f3 = __half22float2(*(__half2*)&v.w);
                    acc[0] += pw * f0.x; acc[1] += pw * f0.y;
                    acc[2] += pw * f1.x; acc[3] += pw * f1.y;
                    acc[4] += pw * f2.x; acc[5] += pw * f2.y;
                    acc[6] += pw * f3.x; acc[7] += pw * f3.y;
                }
            }
            s = warpSumF(s);
            float inv = __fdividef(1.f, g_sp[node] + s + 1e-16f);
            #pragma unroll
            for (int j = 0; j < 8; j++) {
                acc[j] += __shfl_xor_sync(0xffffffffu, acc[j], 4);
                acc[j] += __shfl_xor_sync(0xffffffffu, acc[j], 8);
                acc[j] += __shfl_xor_sync(0xffffffffu, acc[j], 16);
            }
            if (eg == 0) {
                #pragma unroll
                for (int j = 0; j < 8; j++) sh_h[warp][fq * 8 + j] = acc[j];
            }
            __syncwarp();
            h = (g_hp[(size_t)node * 32 + lane] + sh_h[warp][lane]) * inv;
        }
        h += bias[lane] + res;
        g_h[(size_t)node * 32 + lane] = h;
    }
    double v = active ? (double)h : 0.0;
    double v2 = active ? (double)h * (double)h : 0.0;
    v = warpSumD(v); v2 = warpSumD(v2);
    __shared__ double sh[2][8];
    if (lane == 0) { sh[0][warp] = v; sh[1][warp] = v2; }
    __syncthreads();
    if (threadIdx.x == 0) {
        double a = 0, b = 0;
        for (int ww = 0; ww < 8; ww++) { a += sh[0][ww]; b += sh[1][ww]; }
        atomicAdd(&g_stats[layer][0], a);
        atomicAdd(&g_stats[layer][1], b);
    }
}

__global__ void k_lnact(const float* __restrict__ lnw, const float* __restrict__ lnb,
                        int layer, int n, int dopool) {
    __shared__ float s_mu, s_std;
    if (threadIdx.x == 0) {
        double cnt = (double)n * 32.0;
        double mu = g_stats[layer][0] / cnt;
        double var = g_stats[layer][1] / cnt - mu * mu;
        if (var < 0.0) var = 0.0;
        s_mu = (float)mu;
        s_std = (float)sqrt(var) + 1e-5f;
    }
    __syncthreads();
    float mu = s_mu, stdpe = s_std;
    int f = threadIdx.x & 31;
    float w = lnw[f], b = lnb[f];
    double acc = 0.0;
    int total = n * 32;
    for (int i = blockIdx.x * blockDim.x + threadIdx.x; i < total; i += gridDim.x * blockDim.x) {
        float t = (g_h[i] - mu) / stdpe * w + b;
        float sig = 1.f / (1.f + __expf(-t));
        float xo = t * sig;
        g_x[i] = xo;
        acc += (double)xo;
    }
    if (dopool) {
        __shared__ double shd[8][32];
        int warp = threadIdx.x >> 5;
        shd[warp][f] = acc;
        __syncthreads();
        if (warp == 0) {
            double a = 0;
            for (int ww = 0; ww < 8; ww++) a += shd[ww][f];
            atomicAdd(&g_pool[f], a);
        }
    }
}

__global__ void k_final(const float* __restrict__ W, const float* __restrict__ b,
                        float* __restrict__ out, int n) {
    __shared__ float x3[32];
    if (threadIdx.x < 32) x3[threadIdx.x] = (float)(g_pool[threadIdx.x] / (double)n);
    __syncthreads();
    int j = threadIdx.x;
    if (j < 256) {
        float acc = b[j];
        #pragma unroll
        for (int o = 0; o < 32; o++) acc += x3[o] * W[j * 32 + o];
        float sig = 1.f / (1.f + expf(-acc));
        out[j] = acc * sig;
    }
}

extern "C" void kernel_launch(void* const* d_in, const int* in_sizes, int n_in,
                              void* d_out, int out_size) {
    const float* db1  = (const float*)d_in[0];
    const int*   ei   = (const int*)d_in[2];
    const int*   et   = (const int*)d_in[3];
    const float* W0   = (const float*)d_in[6];
    const float* q0   = (const float*)d_in[7];
    const float* k0   = (const float*)d_in[8];
    const float* b0   = (const float*)d_in[9];
    const float* Ws   = (const float*)d_in[10];
    const float* qs   = (const float*)d_in[11];
    const float* ks   = (const float*)d_in[12];
    const float* bs   = (const float*)d_in[13];
    const float* lnw  = (const float*)d_in[14];
    const float* lnb  = (const float*)d_in[15];
    const float* ln1w = (const float*)d_in[16];
    const float* ln1b = (const float*)d_in[17];
    const float* l1W  = (const float*)d_in[18];
    const float* l1b  = (const float*)d_in[19];
    float* out = (float*)d_out;
    int n = in_sizes[0] / 35;
    int e = in_sizes[3];
    int ntot = n * 16;
    int nb16 = (ntot + 255) / 256;

    k_zero<<<512, 256>>>();
    k_stats<<<512, 256>>>(db1, n);
    k_eigh<<<1, 1>>>(n);
    k_buildx0<<<(n * 36 + 255) / 256, 256>>>(db1, ln1w, ln1b, n);

    k_hist<<<(e + 255) / 256, 256>>>(ei, et, e);
    k_scanA<<<nb16, 256>>>(ntot);
    k_scanB<<<1, 512>>>(nb16);
    k_scanC<<<nb16, 256>>>(ntot, n, e);
    k_scatter<<<(e + 255) / 256, 256>>>(ei, et, e);

    int gg = (n + 127) / 128;
    for (int l = 0; l < NLAY; l++) {
        const float* bias = (l == 0) ? b0 : bs + (l - 1) * 32;
        if (l == 0) {
            k_gemm<35, 36, 48><<<gg, 128>>>(W0, q0, k0, n);
        } else {
            k_gemm<32, 32, 32><<<gg, 128>>>(Ws + (size_t)(l - 1) * RREL * 32 * 32,
                                            qs + (l - 1) * 32, ks + (l - 1) * 32, n);
        }
        k_edgeA<<<(n + 7) / 8, 256>>>(n);
        k_edgeB<<<(n + 7) / 8, 256>>>(bias, l, n);
        k_lnact<<<512, 256>>>(lnw + l * 32, lnb + l * 32, l, n, (l == NLAY - 1) ? 1 : 0);
    }
    k_final<<<1, 256>>>(l1W, l1b, out, n);
}

// round 15
// speedup vs baseline: 1.0803x; 1.0803x over previous
#include <cuda_runtime.h>
#include <cuda_fp16.h>
#include <math.h>
#include <stdint.h>

#define NMAX 100000
#define EMAX 3200000
#define RREL 15
#define NLAY 4
#define NB16 (NMAX * 16)

__device__ __half g_xr[(size_t)RREL * NMAX * 32];
__device__ float g_x0[NMAX * 36];
__device__ float g_x[NMAX * 32];
__device__ float g_h[NMAX * 32];
__device__ float g_qv[NMAX * 16];
__device__ int   g_rowptr[NMAX + 1];
__device__ int   g_cursor16[NB16];
__device__ int   g_count16[NB16];
__device__ int   g_rp16[NB16];
__device__ int   g_epack[EMAX];
__device__ int   g_bsum[6400];
__device__ int   g_boff[6400];
__device__ double g_stats[NLAY][2];
__device__ double g_pool[32];
__device__ double g_psum[3];
__device__ double g_M[6];
__device__ unsigned int g_mnkey[3], g_mxkey[3];
__device__ float  g_pmean[3];
__device__ float g_V[9];
__device__ float g_pscale;
__device__ double g_fstats[2];
__device__ float  g_fp[2];

__device__ __forceinline__ double warpSumD(double v) {
    for (int o = 16; o > 0; o >>= 1) v += __shfl_down_sync(0xffffffffu, v, o);
    return v;
}
__device__ __forceinline__ float warpSumF(float v) {
    for (int o = 16; o > 0; o >>= 1) v += __shfl_xor_sync(0xffffffffu, v, o);
    return v;
}
__device__ __forceinline__ unsigned int fkey(float f) {
    unsigned int u = __float_as_uint(f);
    return (u & 0x80000000u) ? ~u : (u | 0x80000000u);
}
__device__ __forceinline__ float funkey(unsigned int k) {
    return (k & 0x80000000u) ? __uint_as_float(k ^ 0x80000000u) : __uint_as_float(~k);
}

__device__ __forceinline__ void mma16816(float& d0, float& d1, float& d2, float& d3,
    uint32_t a0, uint32_t a1, uint32_t a2, uint32_t a3, uint32_t b0, uint32_t b1) {
    asm volatile("mma.sync.aligned.m16n8k16.row.col.f32.f16.f16.f32 "
        "{%0,%1,%2,%3}, {%4,%5,%6,%7}, {%8,%9}, {%0,%1,%2,%3};"
        : "+f"(d0), "+f"(d1), "+f"(d2), "+f"(d3)
        : "r"(a0), "r"(a1), "r"(a2), "r"(a3), "r"(b0), "r"(b1));
}

__global__ void k_zero() {
    int i = blockIdx.x * blockDim.x + threadIdx.x;
    int stride = gridDim.x * blockDim.x;
    for (int j = i; j < NB16; j += stride) g_count16[j] = 0;
    if (i == 0) {
        for (int l = 0; l < NLAY; l++) { g_stats[l][0] = 0.0; g_stats[l][1] = 0.0; }
        for (int o = 0; o < 32; o++) g_pool[o] = 0.0;
        for (int c = 0; c < 3; c++) { g_psum[c] = 0.0; g_mnkey[c] = 0xFFFFFFFFu; g_mxkey[c] = 0u; }
        for (int c = 0; c < 6; c++) g_M[c] = 0.0;
        g_fstats[0] = 0.0; g_fstats[1] = 0.0;
    }
}

__global__ void k_stats(const float* __restrict__ d, int n) {
    int gtid = blockIdx.x * blockDim.x + threadIdx.x;
    int stride = gridDim.x * blockDim.x;
    double s0 = 0, s1 = 0, s2 = 0;
    double r00 = 0, r01 = 0, r02 = 0, r11 = 0, r12 = 0, r22 = 0;
    float mn0 = 3e38f, mn1 = 3e38f, mn2 = 3e38f;
    float mx0 = -3e38f, mx1 = -3e38f, mx2 = -3e38f;
    for (int i = gtid; i < n; i += stride) {
        float x = d[i * 35 + 0], y = d[i * 35 + 1], z = d[i * 35 + 2];
        double dx = x, dy = y, dz = z;
        s0 += dx; s1 += dy; s2 += dz;
        r00 += dx * dx; r01 += dx * dy; r02 += dx * dz;
        r11 += dy * dy; r12 += dy * dz; r22 += dz * dz;
        mn0 = fminf(mn0, x); mx0 = fmaxf(mx0, x);
        mn1 = fminf(mn1, y); mx1 = fmaxf(mx1, y);
        mn2 = fminf(mn2, z); mx2 = fmaxf(mx2, z);
    }
    double fs = 0, fss = 0;
    int total = n * 35;
    int q4 = total >> 2;
    const float4* d4 = (const float4*)d;
    for (int j = gtid; j < q4; j += stride) {
        float4 v = d4[j];
        int idx = j * 4;
        int c = idx - (idx / 35) * 35;
        if (c >= 3) { double t = v.x; fs += t; fss += t * t; }
        c = (c == 34) ? 0 : c + 1;
        if (c >= 3) { double t = v.y; fs += t; fss += t * t; }
        c = (c == 34) ? 0 : c + 1;
        if (c >= 3) { double t = v.z; fs += t; fss += t * t; }
        c = (c == 34) ? 0 : c + 1;
        if (c >= 3) { double t = v.w; fs += t; fss += t * t; }
    }
    if (gtid == 0) {
        for (int idx = q4 * 4; idx < total; idx++) {
            int c = idx - (idx / 35) * 35;
            if (c >= 3) { double t = d[idx]; fs += t; fss += t * t; }
        }
    }
    s0 = warpSumD(s0); s1 = warpSumD(s1); s2 = warpSumD(s2);
    r00 = warpSumD(r00); r01 = warpSumD(r01); r02 = warpSumD(r02);
    r11 = warpSumD(r11); r12 = warpSumD(r12); r22 = warpSumD(r22);
    fs = warpSumD(fs); fss = warpSumD(fss);
    for (int o = 16; o > 0; o >>= 1) {
        mn0 = fminf(mn0, __shfl_down_sync(0xffffffffu, mn0, o));
        mn1 = fminf(mn1, __shfl_down_sync(0xffffffffu, mn1, o));
        mn2 = fminf(mn2, __shfl_down_sync(0xffffffffu, mn2, o));
        mx0 = fmaxf(mx0, __shfl_down_sync(0xffffffffu, mx0, o));
        mx1 = fmaxf(mx1, __shfl_down_sync(0xffffffffu, mx1, o));
        mx2 = fmaxf(mx2, __shfl_down_sync(0xffffffffu, mx2, o));
    }
    if ((threadIdx.x & 31) == 0) {
        atomicAdd(&g_psum[0], s0); atomicAdd(&g_psum[1], s1); atomicAdd(&g_psum[2], s2);
        atomicAdd(&g_M[0], r00); atomicAdd(&g_M[1], r01); atomicAdd(&g_M[2], r02);
        atomicAdd(&g_M[3], r11); atomicAdd(&g_M[4], r12); atomicAdd(&g_M[5], r22);
        atomicAdd(&g_fstats[0], fs); atomicAdd(&g_fstats[1], fss);
        atomicMin(&g_mnkey[0], fkey(mn0)); atomicMax(&g_mxkey[0], fkey(mx0));
        atomicMin(&g_mnkey[1], fkey(mn1)); atomicMax(&g_mxkey[1], fkey(mx1));
        atomicMin(&g_mnkey[2], fkey(mn2)); atomicMax(&g_mxkey[2], fkey(mx2));
    }
}

// ---- LAPACK ssyevd-style path in float: sytd2('L') -> steqr('I') -> V=Q*Z ----
__device__ void dev_slartg(float f, float g, float* cs, float* sn, float* r) {
    if (g == 0.f) { *cs = 1.f; *sn = 0.f; *r = f; }
    else if (f == 0.f) { *cs = 0.f; *sn = 1.f; *r = g; }
    else {
        float rr = sqrtf(f * f + g * g);
        float c = f / rr, s = g / rr;
        if (fabsf(f) > fabsf(g) && c < 0.f) { c = -c; s = -s; rr = -rr; }
        *cs = c; *sn = s; *r = rr;
    }
}

__device__ void dev_slaev2(float a, float b, float c,
                           float* rt1, float* rt2, float* cs1, float* sn1) {
    float sm = a + c, df = a - c;
    float adf = fabsf(df), tb = b + b, ab = fabsf(tb);
    float acmx, acmn;
    if (fabsf(a) > fabsf(c)) { acmx = a; acmn = c; } else { acmx = c; acmn = a; }
    float rt;
    if (adf > ab) rt = adf * sqrtf(1.f + (ab / adf) * (ab / adf));
    else if (adf < ab) rt = ab * sqrtf(1.f + (adf / ab) * (adf / ab));
    else rt = ab * sqrtf(2.f);
    int sgn1;
    if (sm < 0.f) { *rt1 = 0.5f * (sm - rt); sgn1 = -1; *rt2 = (acmx / *rt1) * acmn - (b / *rt1) * b; }
    else if (sm > 0.f) { *rt1 = 0.5f * (sm + rt); sgn1 = 1; *rt2 = (acmx / *rt1) * acmn - (b / *rt1) * b; }
    else { *rt1 = 0.5f * rt; *rt2 = -0.5f * rt; sgn1 = 1; }
    float cs; int sgn2;
    if (df >= 0.f) { cs = df + rt; sgn2 = 1; } else { cs = df - rt; sgn2 = -1; }
    float acs = fabsf(cs);
    if (acs > ab) {
        float ct = -tb / cs;
        *sn1 = 1.f / sqrtf(1.f + ct * ct);
        *cs1 = ct * (*sn1);
    } else {
        if (ab == 0.f) { *cs1 = 1.f; *sn1 = 0.f; }
        else {
            float tn = -cs / tb;
            *cs1 = 1.f / sqrtf(1.f + tn * tn);
            *sn1 = tn * (*cs1);
        }
    }
    if (sgn1 == sgn2) { float tn = *cs1; *cs1 = -(*sn1); *sn1 = tn; }
}

__global__ void k_eigh(int nn) {
    if (threadIdx.x != 0) return;
    double mu0 = g_psum[0] / (double)nn, mu1 = g_psum[1] / (double)nn, mu2 = g_psum[2] / (double)nn;
    g_pmean[0] = (float)mu0; g_pmean[1] = (float)mu1; g_pmean[2] = (float)mu2;
    {
        double cnt = (double)nn * 32.0;
        double mu = g_fstats[0] / cnt;
        double var = g_fstats[1] / cnt - mu * mu;
        if (var < 0.0) var = 0.0;
        g_fp[0] = (float)mu;
        g_fp[1] = (float)sqrt(var) + 1e-5f;
    }
    double mus[3] = {mu0, mu1, mu2};
    float mxab = 0.f;
    for (int c = 0; c < 3; c++) {
        float hi = funkey(g_mxkey[c]) - (float)mus[c];
        float lo = (float)mus[c] - funkey(g_mnkey[c]);
        mxab = fmaxf(mxab, fmaxf(hi, lo));
    }
    float sc = (1.0f / mxab) * 0.999999f;
    g_pscale = sc;
    double s2d = (double)sc * (double)sc;
    double N = (double)nn;
    float a00 = (float)((g_M[0] - N * mu0 * mu0) * s2d);
    float a01 = (float)((g_M[1] - N * mu0 * mu1) * s2d);
    float a02 = (float)((g_M[2] - N * mu0 * mu2) * s2d);
    float a11 = (float)((g_M[3] - N * mu1 * mu1) * s2d);
    float a12 = (float)((g_M[4] - N * mu1 * mu2) * s2d);
    float a22 = (float)((g_M[5] - N * mu2 * mu2) * s2d);

    float d[4], e[3];
    float tau = 0.f, v1 = 0.f;
    {
        float alpha = a01;
        float x = a02;
        float xnorm = fabsf(x);
        float beta;
        if (xnorm == 0.f) { tau = 0.f; beta = alpha; }
        else {
            float hy = sqrtf(alpha * alpha + xnorm * xnorm);
            beta = (alpha >= 0.f) ? -hy : hy;
            tau = (beta - alpha) / beta;
            v1 = x / (alpha - beta);
        }
        e[1] = beta;
        float nd11 = a11, nd12 = a12, nd22 = a22;
        if (tau != 0.f) {
            float w0 = tau * (a11 + a12 * v1);
            float w1 = tau * (a12 + a22 * v1);
            float al = -0.5f * tau * (w0 + w1 * v1);
            w0 += al;
            w1 += al * v1;
            nd11 = a11 - 2.f * w0;
            nd12 = a12 - (w1 + w0 * v1);
            nd22 = a22 - 2.f * v1 * w1;
        }
        d[1] = a00; d[2] = nd11; d[3] = nd22;
        e[2] = nd12;
    }

    const int n = 3;
    float Z[4][4];
    for (int i = 1; i <= 3; i++)
        for (int j = 1; j <= 3; j++) Z[i][j] = (i == j) ? 1.f : 0.f;
    float eps = 1.1920929e-7f;
    float eps2 = eps * eps;
    float safmin = 1.17549435e-38f;
    int nmaxit = n * 30, jtot = 0;
    float wc[4], ws[4];
    int l1 = 1;
    while (true) {
        if (l1 > n) break;
        if (l1 > 1) e[l1 - 1] = 0.f;
        int m;
        if (l1 <= n - 1) {
            for (m = l1; m <= n - 1; m++) {
                float tst = fabsf(e[m]);
                if (tst == 0.f) break;
                if (tst <= (sqrtf(fabsf(d[m])) * sqrtf(fabsf(d[m + 1]))) * eps) { e[m] = 0.f; break; }
            }
        } else m = n;
        int l = l1, lend = m;
        l1 = m + 1;
        if (lend == l) continue;
        if (fabsf(d[lend]) < fabsf(d[l])) { int t = lend; lend = l; l = t; }
        if (lend > l) {
            while (true) {
                int mm;
                if (l != lend) {
                    for (mm = l; mm <= lend - 1; mm++) {
                        float tst = e[mm] * e[mm];
                        if (tst <= (eps2 * fabsf(d[mm]) * fabsf(d[mm + 1]) + safmin)) break;
                    }
                } else mm = lend;
                m = mm;
                if (m < lend) e[m] = 0.f;
                float p = d[l];
                if (m == l) { d[l] = p; l = l + 1; if (l <= lend) continue; else break; }
                if (m == l + 1) {
                    float rt1, rt2, c, s;
                    dev_slaev2(d[l], e[l], d[l + 1], &rt1, &rt2, &c, &s);
                    for (int i = 1; i <= n; i++) {
                        float temp = Z[i][l + 1];
                        Z[i][l + 1] = c * temp - s * Z[i][l];
                        Z[i][l] = s * temp + c * Z[i][l];
                    }
                    d[l] = rt1; d[l + 1] = rt2; e[l] = 0.f;
                    l = l + 2;
                    if (l <= lend) continue; else break;
                }
                if (jtot == nmaxit) break;
                jtot++;
                float g = (d[l + 1] - p) / (2.f * e[l]);
                float r = sqrtf(g * g + 1.f);
                float sg = (g >= 0.f) ? fabsf(r) : -fabsf(r);
                g = d[m] - p + e[l] / (g + sg);
                float s = 1.f, c = 1.f;
                p = 0.f;
                for (int i = m - 1; i >= l; i--) {
                    float f = s * e[i];
                    float b = c * e[i];
                    dev_slartg(g, f, &c, &s, &r);
                    if (i != m - 1) e[i + 1] = r;
                    g = d[i + 1] - p;
                    r = (d[i] - g) * s + 2.f * c * b;
                    p = s * r;
                    d[i + 1] = g + p;
                    g = c * r - b;
                    wc[i] = c; ws[i] = -s;
                }
                for (int j = m - 1; j >= l; j--) {
                    float cj = wc[j], sj = ws[j];
                    for (int i = 1; i <= n; i++) {
                        float temp = Z[i][j + 1];
                        Z[i][j + 1] = cj * temp - sj * Z[i][j];
                        Z[i][j] = sj * temp + cj * Z[i][j];
                    }
                }
                d[l] = d[l] - p;
                e[l] = g;
            }
        } else {
            while (true) {
                int mm;
                if (l != lend) {
                    for (mm = l; mm >= lend + 1; mm--) {
                        float tst = e[mm - 1] * e[mm - 1];
                        if (tst <= (eps2 * fabsf(d[mm]) * fabsf(d[mm - 1]) + safmin)) break;
                    }
                } else mm = lend;
                m = mm;
                if (m > lend) e[m - 1] = 0.f;
                float p = d[l];
                if (m == l) { d[l] = p; l = l - 1; if (l >= lend) continue; else break; }
                if (m == l - 1) {
                    float rt1, rt2, c, s;
                    dev_slaev2(d[l - 1], e[l - 1], d[l], &rt1, &rt2, &c, &s);
                    for (int i = 1; i <= n; i++) {
                        float temp = Z[i][l];
                        Z[i][l] = c * temp - s * Z[i][l - 1];
                        Z[i][l - 1] = s * temp + c * Z[i][l - 1];
                    }
                    d[l - 1] = rt1; d[l] = rt2; e[l - 1] = 0.f;
                    l = l - 2;
                    if (l >= lend) continue; else break;
                }
                if (jtot == nmaxit) break;
                jtot++;
                float g = (d[l - 1] - p) / (2.f * e[l - 1]);
                float r = sqrtf(g * g + 1.f);
                float sg = (g >= 0.f) ? fabsf(r) : -fabsf(r);
                g = d[m] - p + e[l - 1] / (g + sg);
                float s = 1.f, c = 1.f;
                p = 0.f;
                for (int i = m; i <= l - 1; i++) {
                    float f = s * e[i];
                    float b = c * e[i];
                    dev_slartg(g, f, &c, &s, &r);
                    if (i != m) e[i - 1] = r;
                    g = d[i] - p;
                    r = (d[i + 1] - g) * s + 2.f * c * b;
                    p = s * r;
                    d[i] = g + p;
                    g = c * r - b;
                    wc[i] = c; ws[i] = s;
                }
                for (int j = m; j <= l - 1; j++) {
                    float cj = wc[j], sj = ws[j];
                    for (int i = 1; i <= n; i++) {
                        float temp = Z[i][j + 1];
                        Z[i][j + 1] = cj * temp - sj * Z[i][j];
                        Z[i][j] = sj * temp + cj * Z[i][j];
                    }
                }
                d[l] = d[l] - p;
                e[l - 1] = g;
            }
        }
    }
    for (int ii = 2; ii <= n; ii++) {
        int i = ii - 1, k = i;
        float p = d[i];
        for (int j = ii; j <= n; j++) if (d[j] < p) { k = j; p = d[j]; }
        if (k != i) {
            d[k] = d[i]; d[i] = p;
            for (int rr = 1; rr <= n; rr++) { float t = Z[rr][i]; Z[rr][i] = Z[rr][k]; Z[rr][k] = t; }
        }
    }
    float Q[4][4];
    Q[1][1] = 1.f; Q[1][2] = 0.f; Q[1][3] = 0.f;
    Q[2][1] = 0.f; Q[3][1] = 0.f;
    Q[2][2] = 1.f - tau;
    Q[2][3] = -tau * v1;
    Q[3][2] = -tau * v1;
    Q[3][3] = 1.f - tau * v1 * v1;
    for (int i = 1; i <= 3; i++)
        for (int j = 1; j <= 3; j++) {
            float acc = 0.f;
            for (int k = 1; k <= 3; k++) acc += Q[i][k] * Z[k][j];
            g_V[(i - 1) * 3 + (j - 1)] = acc;
        }
}

__global__ void k_buildx0(const float* __restrict__ d, const float* __restrict__ ln1w,
                          const float* __restrict__ ln1b, int n) {
    int idx = blockIdx.x * blockDim.x + threadIdx.x;
    if (idx >= n * 36) return;
    int node = idx / 36, j = idx % 36;
    float val;
    if (j < 3) {
        float sc = g_pscale;
        float a = (d[node * 35 + 0] - g_pmean[0]) * sc;
        float b = (d[node * 35 + 1] - g_pmean[1]) * sc;
        float c = (d[node * 35 + 2] - g_pmean[2]) * sc;
        val = a * g_V[0 + j] + b * g_V[3 + j] + c * g_V[6 + j];
    } else if (j < 35) {
        val = (d[node * 35 + j] - g_fp[0]) / g_fp[1] * ln1w[j - 3] + ln1b[j - 3];
    } else val = 0.f;
    g_x0[idx] = val;
}

__global__ void k_hist(const int* __restrict__ ei, const int* __restrict__ et, int e) {
    int i = blockIdx.x * blockDim.x + threadIdx.x;
    if (i < e) atomicAdd(&g_count16[ei[e + i] * 16 + et[i]], 1);
}

__global__ void k_scanA(int ntot) {
    __shared__ int ws[8];
    int b = blockIdx.x, tid = threadIdx.x, lane = tid & 31, w = tid >> 5;
    int i = b * 256 + tid;
    int v = (i < ntot) ? g_count16[i] : 0;
    int x = v;
    for (int o = 1; o < 32; o <<= 1) {
        int y = __shfl_up_sync(0xffffffffu, x, o);
        if (lane >= o) x += y;
    }
    if (lane == 31) ws[w] = x;
    __syncthreads();
    if (tid == 0) {
        int run = 0;
        for (int j = 0; j < 8; j++) { int t = ws[j]; ws[j] = run; run += t; }
    }
    __syncthreads();
    int excl = x - v + ws[w];
    if (i < ntot) g_rp16[i] = excl;
    if (tid == 255) g_bsum[b] = excl + v;
}

__global__ void k_scanB(int nb) {
    __shared__ int sd[512];
    __shared__ int s_carry;
    int tid = threadIdx.x;
    if (tid == 0) s_carry = 0;
    __syncthreads();
    for (int b0 = 0; b0 < nb; b0 += 512) {
        int i = b0 + tid;
        int v = (i < nb) ? g_bsum[i] : 0;
        sd[tid] = v;
        __syncthreads();
        for (int o = 1; o < 512; o <<= 1) {
            int tv = (tid >= o) ? sd[tid - o] : 0;
            __syncthreads();
            sd[tid] += tv;
            __syncthreads();
        }
        int c = s_carry;
        if (i < nb) g_boff[i] = c + sd[tid] - v;
        __syncthreads();
        if (tid == 511) s_carry = c + sd[511];
        __syncthreads();
    }
}

__global__ void k_scanC(int ntot, int n, int e) {
    int i = blockIdx.x * blockDim.x + threadIdx.x;
    if (i >= ntot) return;
    int rp = g_rp16[i] + g_boff[i >> 8];
    g_cursor16[i] = rp;
    if ((i & 15) == 0) g_rowptr[i >> 4] = rp;
    if (i == 0) g_rowptr[n] = e;
}

__global__ void k_scatter(const int* __restrict__ ei, const int* __restrict__ et, int e) {
    int i = blockIdx.x * blockDim.x + threadIdx.x;
    if (i >= e) return;
    int r = et[i];
    int pos = atomicAdd(&g_cursor16[ei[e + i] * 16 + r], 1);
    g_epack[pos] = ei[i] | (r << 20);
}

// Tensor-core GEMM: xr[r] = x @ W[r] (fp16 in, fp32 acc), qv fused epilogue.
template <int F, int STRIDE, int KP>
__global__ void k_gemm(const float* __restrict__ W, const float* __restrict__ qvec, int n) {
    __shared__ __half xs[128][56];
    __shared__ __half wt[32][56];
    __shared__ __half xout[128][36];
    __shared__ float sq[32];
    int tid = threadIdx.x;
    int w = tid >> 5, lane = tid & 31, g = lane >> 2, t = lane & 3;
    int base = blockIdx.x * 128;
    const float* xbuf = (F == 35) ? g_x0 : g_x;

    for (int idx = tid; idx < 128 * KP; idx += 128) {
        int nl = idx / KP, f = idx % KP;
        int node = base + nl;
        float v = (f < F && node < n) ? xbuf[(size_t)node * STRIDE + f] : 0.f;
        xs[nl][f] = __float2half(v);
    }
    if (tid < 32) sq[tid] = qvec[tid];

    for (int r = 0; r < RREL; r++) {
        __syncthreads();
        for (int idx = tid; idx < 32 * KP; idx += 128) {
            int o = idx / KP, f = idx % KP;
            wt[o][f] = (f < F) ? __float2half(W[((size_t)r * F + f) * 32 + o]) : __float2half(0.f);
        }
        __syncthreads();
        for (int mt = 0; mt < 2; mt++) {
            int rowbase = w * 32 + mt * 16;
            float qp0 = 0, qp1 = 0;
            for (int nt = 0; nt < 4; nt++) {
                float d0 = 0, d1 = 0, d2 = 0, d3 = 0;
                #pragma unroll
                for (int ks = 0; ks < KP / 16; ks++) {
                    uint32_t a0 = *(const uint32_t*)&xs[rowbase + g][2 * t + ks * 16];
                    uint32_t a1 = *(const uint32_t*)&xs[rowbase + g + 8][2 * t + ks * 16];
                    uint32_t a2 = *(const uint32_t*)&xs[rowbase + g][2 * t + 8 + ks * 16];
                    uint32_t a3 = *(const uint32_t*)&xs[rowbase + g + 8][2 * t + 8 + ks * 16];
                    uint32_t b0 = *(const uint32_t*)&wt[nt * 8 + g][2 * t + ks * 16];
                    uint32_t b1 = *(const uint32_t*)&wt[nt * 8 + g][2 * t + 8 + ks * 16];
                    mma16816(d0, d1, d2, d3, a0, a1, a2, a3, b0, b1);
                }
                int c = nt * 8 + 2 * t;
                *(__half2*)&xout[rowbase + g][c] = __floats2half2_rn(d0, d1);
                *(__half2*)&xout[rowbase + g + 8][c] = __floats2half2_rn(d2, d3);
                qp0 += d0 * sq[c] + d1 * sq[c + 1];
                qp1 += d2 * sq[c] + d3 * sq[c + 1];
            }
            qp0 += __shfl_xor_sync(0xffffffffu, qp0, 1); qp0 += __shfl_xor_sync(0xffffffffu, qp0, 2);
            qp1 += __shfl_xor_sync(0xffffffffu, qp1, 1); qp1 += __shfl_xor_sync(0xffffffffu, qp1, 2);
            if (t == 0) {
                int n0 = base + rowbase + g, n1 = n0 + 8;
                if (n0 < n) g_qv[n0 * 16 + r] = qp0;
                if (n1 < n) g_qv[n1 * 16 + r] = qp1;
            }
        }
        __syncwarp();
        #pragma unroll
        for (int i = 0; i < 16; i++) {
            int rl = w * 32 + 2 * i + (lane >> 4);
            int node = base + rl;
            if (node < n) {
                uint32_t v = *(const uint32_t*)&xout[rl][(lane & 15) * 2];
                *(uint32_t*)&g_xr[((size_t)r * n + node) * 32 + (lane & 15) * 2] = v;
            }
        }
    }
}

// ONE-PASS edge kernel: kj computed IN-REGISTER from the gathered xr row —
// no kv array, no dependent epack->kv chain, ~45% fewer random wavefronts.
__global__ void k_edge(const float* __restrict__ bias, const float* __restrict__ kvec,
                       int layer, int n) {
    int warp = threadIdx.x >> 5, lane = threadIdx.x & 31;
    int node = blockIdx.x * 8 + warp;
    float h = 0.f;
    bool active = node < n;
    __shared__ float sh_qv[8][16];
    __shared__ float sh_h[8][32];
    __shared__ float sh_k[32];
    if (threadIdx.x < 32) sh_k[threadIdx.x] = kvec[threadIdx.x];
    if (active && lane < 16) sh_qv[warp][lane] = g_qv[node * 16 + lane];
    __syncthreads();
    if (active) {
        int beg = g_rowptr[node], end = g_rowptr[node + 1];
        float res = (layer > 0) ? g_x[(size_t)node * 32 + lane] : 0.f;
        if (end > beg) {
            int fq = lane & 3, eg = lane >> 2;
            float kc[8];
            #pragma unroll
            for (int j = 0; j < 8; j++) kc[j] = sh_k[fq * 8 + j];
            float s = 0.f;
            float acc[8];
            #pragma unroll
            for (int j = 0; j < 8; j++) acc[j] = 0.f;
            for (int cb = beg; cb < end; cb += 32) {
                int i = cb + lane;
                int p = (i < end) ? g_epack[i] : 0;
                int cnt = min(32, end - cb);
                for (int jb = 0; jb < cnt; jb += 8) {
                    int sl = jb + eg;
                    int pp = __shfl_sync(0xffffffffu, p, sl & 31);
                    bool ok = (sl < cnt);
                    int r = pp >> 20, src = pp & 0xFFFFF;
                    uint4 v = *(const uint4*)&g_xr[((size_t)(r * n + src)) * 32 + fq * 8];
                    float2 f0 = __half22float2(*(__half2*)&v.x);
                    float2 f1 = __half22float2(*(__half2*)&v.y);
                    float2 f2 = __half22float2(*(__half2*)&v.z);
                    float2 f3 = __half22float2(*(__half2*)&v.w);
                    float kj = f0.x * kc[0] + f0.y * kc[1] + f1.x * kc[2] + f1.y * kc[3]
                             + f2.x * kc[4] + f2.y * kc[5] + f3.x * kc[6] + f3.y * kc[7];
                    kj += __shfl_xor_sync(0xffffffffu, kj, 1);
                    kj += __shfl_xor_sync(0xffffffffu, kj, 2);
                    float a = sh_qv[warp][r] + kj;
                    a = (a > 0.f) ? a : 0.2f * a;
                    float al = ok ? __expf(a) : 0.f;
                    if (fq == 0) s += al;
                    acc[0] += al * f0.x; acc[1] += al * f0.y;
                    acc[2] += al * f1.x; acc[3] += al * f1.y;
                    acc[4] += al * f2.x; acc[5] += al * f2.y;
                    acc[6] += al * f3.x; acc[7] += al * f3.y;
                }
            }
            s = warpSumF(s);
            float inv = __fdividef(1.f, s + 1e-16f);
            #pragma unroll
            for (int j = 0; j < 8; j++) {
                acc[j] += __shfl_xor_sync(0xffffffffu, acc[j], 4);
                acc[j] += __shfl_xor_sync(0xffffffffu, acc[j], 8);
                acc[j] += __shfl_xor_sync(0xffffffffu, acc[j], 16);
            }
            if (eg == 0) {
                #pragma unroll
                for (int j = 0; j < 8; j++) sh_h[warp][fq * 8 + j] = acc[j] * inv;
            }
            __syncwarp();
            h = sh_h[warp][lane];
        }
        h += bias[lane] + res;
        g_h[(size_t)node * 32 + lane] = h;
    }
    double v = active ? (double)h : 0.0;
    double v2 = active ? (double)h * (double)h : 0.0;
    v = warpSumD(v); v2 = warpSumD(v2);
    __shared__ double sh[2][8];
    if (lane == 0) { sh[0][warp] = v; sh[1][warp] = v2; }
    __syncthreads();
    if (threadIdx.x == 0) {
        double a = 0, b = 0;
        for (int ww = 0; ww < 8; ww++) { a += sh[0][ww]; b += sh[1][ww]; }
        atomicAdd(&g_stats[layer][0], a);
        atomicAdd(&g_stats[layer][1], b);
    }
}

__global__ void k_lnact(const float* __restrict__ lnw, const float* __restrict__ lnb,
                        int layer, int n, int dopool) {
    __shared__ float s_mu, s_std;
    if (threadIdx.x == 0) {
        double cnt = (double)n * 32.0;
        double mu = g_stats[layer][0] / cnt;
        double var = g_stats[layer][1] / cnt - mu * mu;
        if (var < 0.0) var = 0.0;
        s_mu = (float)mu;
        s_std = (float)sqrt(var) + 1e-5f;
    }
    __syncthreads();
    float mu = s_mu, stdpe = s_std;
    int f = threadIdx.x & 31;
    float w = lnw[f], b = lnb[f];
    double acc = 0.0;
    int total = n * 32;
    for (int i = blockIdx.x * blockDim.x + threadIdx.x; i < total; i += gridDim.x * blockDim.x) {
        float t = (g_h[i] - mu) / stdpe * w + b;
        float sig = 1.f / (1.f + __expf(-t));
        float xo = t * sig;
        g_x[i] = xo;
        acc += (double)xo;
    }
    if (dopool) {
        __shared__ double shd[8][32];
        int warp = threadIdx.x >> 5;
        shd[warp][f] = acc;
        __syncthreads();
        if (warp == 0) {
            double a = 0;
            for (int ww = 0; ww < 8; ww++) a += shd[ww][f];
            atomicAdd(&g_pool[f], a);
        }
    }
}

__global__ void k_final(const float* __restrict__ W, const float* __restrict__ b,
                        float* __restrict__ out, int n) {
    __shared__ float x3[32];
    if (threadIdx.x < 32) x3[threadIdx.x] = (float)(g_pool[threadIdx.x] / (double)n);
    __syncthreads();
    int j = threadIdx.x;
    if (j < 256) {
        float acc = b[j];
        #pragma unroll
        for (int o = 0; o < 32; o++) acc += x3[o] * W[j * 32 + o];
        float sig = 1.f / (1.f + expf(-acc));
        out[j] = acc * sig;
    }
}

extern "C" void kernel_launch(void* const* d_in, const int* in_sizes, int n_in,
                              void* d_out, int out_size) {
    const float* db1  = (const float*)d_in[0];
    const int*   ei   = (const int*)d_in[2];
    const int*   et   = (const int*)d_in[3];
    const float* W0   = (const float*)d_in[6];
    const float* q0   = (const float*)d_in[7];
    const float* k0   = (const float*)d_in[8];
    const float* b0   = (const float*)d_in[9];
    const float* Ws   = (const float*)d_in[10];
    const float* qs   = (const float*)d_in[11];
    const float* ks   = (const float*)d_in[12];
    const float* bs   = (const float*)d_in[13];
    const float* lnw  = (const float*)d_in[14];
    const float* lnb  = (const float*)d_in[15];
    const float* ln1w = (const float*)d_in[16];
    const float* ln1b = (const float*)d_in[17];
    const float* l1W  = (const float*)d_in[18];
    const float* l1b  = (const float*)d_in[19];
    float* out = (float*)d_out;
    int n = in_sizes[0] / 35;
    int e = in_sizes[3];
    int ntot = n * 16;
    int nb16 = (ntot + 255) / 256;

    k_zero<<<512, 256>>>();
    k_stats<<<512, 256>>>(db1, n);
    k_eigh<<<1, 1>>>(n);
    k_hist<<<(e + 255) / 256, 256>>>(ei, et, e);     // slot 4 for ncu
    k_buildx0<<<(n * 36 + 255) / 256, 256>>>(db1, ln1w, ln1b, n);
    k_scanA<<<nb16, 256>>>(ntot);
    k_scanB<<<1, 512>>>(nb16);
    k_scanC<<<nb16, 256>>>(ntot, n, e);
    k_scatter<<<(e + 255) / 256, 256>>>(ei, et, e);

    int gg = (n + 127) / 128;
    for (int l = 0; l < NLAY; l++) {
        const float* bias = (l == 0) ? b0 : bs + (l - 1) * 32;
        const float* kv   = (l == 0) ? k0 : ks + (l - 1) * 32;
        if (l == 0) {
            k_gemm<35, 36, 48><<<gg, 128>>>(W0, q0, n);
        } else {
            k_gemm<32, 32, 32><<<gg, 128>>>(Ws + (size_t)(l - 1) * RREL * 32 * 32,
                                            qs + (l - 1) * 32, n);
        }
        k_edge<<<(n + 7) / 8, 256>>>(bias, kv, l, n);
        k_lnact<<<512, 256>>>(lnw + l * 32, lnb + l * 32, l, n, (l == NLAY - 1) ? 1 : 0);
    }
    k_final<<<1, 256>>>(l1W, l1b, out, n);
}

// round 16
// speedup vs baseline: 1.1461x; 1.0609x over previous
#include <cuda_runtime.h>
#include <cuda_fp16.h>
#include <math.h>
#include <stdint.h>

#define NMAX 100000
#define EMAX 3200000
#define RREL 15
#define NLAY 4
#define NB16 (NMAX * 16)

__device__ __half g_xr[(size_t)RREL * NMAX * 32];
__device__ float g_x0[NMAX * 36];
__device__ float g_x[NMAX * 32];
__device__ float g_h[NMAX * 32];
__device__ float g_qv[NMAX * 16];
__device__ float g_kv[NMAX * 16];
__device__ int   g_rowptr[NMAX + 1];
__device__ int   g_cursor16[NB16];
__device__ int   g_count16[NB16];
__device__ int   g_rp16[NB16];
__device__ int   g_epack[EMAX];
__device__ int   g_bsum[6400];
__device__ int   g_boff[6400];
__device__ double g_stats[NLAY][2];
__device__ double g_pool[32];
__device__ double g_psum[3];
__device__ double g_M[6];
__device__ unsigned int g_mnkey[3], g_mxkey[3];
__device__ float  g_pmean[3];
__device__ float g_V[9];
__device__ float g_pscale;
__device__ double g_fstats[2];
__device__ float  g_fp[2];

__device__ __forceinline__ double warpSumD(double v) {
    for (int o = 16; o > 0; o >>= 1) v += __shfl_down_sync(0xffffffffu, v, o);
    return v;
}
__device__ __forceinline__ float warpSumF(float v) {
    for (int o = 16; o > 0; o >>= 1) v += __shfl_xor_sync(0xffffffffu, v, o);
    return v;
}
__device__ __forceinline__ unsigned int fkey(float f) {
    unsigned int u = __float_as_uint(f);
    return (u & 0x80000000u) ? ~u : (u | 0x80000000u);
}
__device__ __forceinline__ float funkey(unsigned int k) {
    return (k & 0x80000000u) ? __uint_as_float(k ^ 0x80000000u) : __uint_as_float(~k);
}

__device__ __forceinline__ void mma16816(float& d0, float& d1, float& d2, float& d3,
    uint32_t a0, uint32_t a1, uint32_t a2, uint32_t a3, uint32_t b0, uint32_t b1) {
    asm volatile("mma.sync.aligned.m16n8k16.row.col.f32.f16.f16.f32 "
        "{%0,%1,%2,%3}, {%4,%5,%6,%7}, {%8,%9}, {%0,%1,%2,%3};"
        : "+f"(d0), "+f"(d1), "+f"(d2), "+f"(d3)
        : "r"(a0), "r"(a1), "r"(a2), "r"(a3), "r"(b0), "r"(b1));
}

__global__ void k_zero() {
    int i = blockIdx.x * blockDim.x + threadIdx.x;
    int stride = gridDim.x * blockDim.x;
    for (int j = i; j < NB16; j += stride) g_count16[j] = 0;
    if (i == 0) {
        for (int l = 0; l < NLAY; l++) { g_stats[l][0] = 0.0; g_stats[l][1] = 0.0; }
        for (int o = 0; o < 32; o++) g_pool[o] = 0.0;
        for (int c = 0; c < 3; c++) { g_psum[c] = 0.0; g_mnkey[c] = 0xFFFFFFFFu; g_mxkey[c] = 0u; }
        for (int c = 0; c < 6; c++) g_M[c] = 0.0;
        g_fstats[0] = 0.0; g_fstats[1] = 0.0;
    }
}

__global__ void k_stats(const float* __restrict__ d, int n) {
    int gtid = blockIdx.x * blockDim.x + threadIdx.x;
    int stride = gridDim.x * blockDim.x;
    double s0 = 0, s1 = 0, s2 = 0;
    double r00 = 0, r01 = 0, r02 = 0, r11 = 0, r12 = 0, r22 = 0;
    float mn0 = 3e38f, mn1 = 3e38f, mn2 = 3e38f;
    float mx0 = -3e38f, mx1 = -3e38f, mx2 = -3e38f;
    for (int i = gtid; i < n; i += stride) {
        float x = d[i * 35 + 0], y = d[i * 35 + 1], z = d[i * 35 + 2];
        double dx = x, dy = y, dz = z;
        s0 += dx; s1 += dy; s2 += dz;
        r00 += dx * dx; r01 += dx * dy; r02 += dx * dz;
        r11 += dy * dy; r12 += dy * dz; r22 += dz * dz;
        mn0 = fminf(mn0, x); mx0 = fmaxf(mx0, x);
        mn1 = fminf(mn1, y); mx1 = fmaxf(mx1, y);
        mn2 = fminf(mn2, z); mx2 = fmaxf(mx2, z);
    }
    double fs = 0, fss = 0;
    int total = n * 35;
    int q4 = total >> 2;
    const float4* d4 = (const float4*)d;
    for (int j = gtid; j < q4; j += stride) {
        float4 v = d4[j];
        int idx = j * 4;
        int c = idx - (idx / 35) * 35;
        if (c >= 3) { double t = v.x; fs += t; fss += t * t; }
        c = (c == 34) ? 0 : c + 1;
        if (c >= 3) { double t = v.y; fs += t; fss += t * t; }
        c = (c == 34) ? 0 : c + 1;
        if (c >= 3) { double t = v.z; fs += t; fss += t * t; }
        c = (c == 34) ? 0 : c + 1;
        if (c >= 3) { double t = v.w; fs += t; fss += t * t; }
    }
    if (gtid == 0) {
        for (int idx = q4 * 4; idx < total; idx++) {
            int c = idx - (idx / 35) * 35;
            if (c >= 3) { double t = d[idx]; fs += t; fss += t * t; }
        }
    }
    s0 = warpSumD(s0); s1 = warpSumD(s1); s2 = warpSumD(s2);
    r00 = warpSumD(r00); r01 = warpSumD(r01); r02 = warpSumD(r02);
    r11 = warpSumD(r11); r12 = warpSumD(r12); r22 = warpSumD(r22);
    fs = warpSumD(fs); fss = warpSumD(fss);
    for (int o = 16; o > 0; o >>= 1) {
        mn0 = fminf(mn0, __shfl_down_sync(0xffffffffu, mn0, o));
        mn1 = fminf(mn1, __shfl_down_sync(0xffffffffu, mn1, o));
        mn2 = fminf(mn2, __shfl_down_sync(0xffffffffu, mn2, o));
        mx0 = fmaxf(mx0, __shfl_down_sync(0xffffffffu, mx0, o));
        mx1 = fmaxf(mx1, __shfl_down_sync(0xffffffffu, mx1, o));
        mx2 = fmaxf(mx2, __shfl_down_sync(0xffffffffu, mx2, o));
    }
    if ((threadIdx.x & 31) == 0) {
        atomicAdd(&g_psum[0], s0); atomicAdd(&g_psum[1], s1); atomicAdd(&g_psum[2], s2);
        atomicAdd(&g_M[0], r00); atomicAdd(&g_M[1], r01); atomicAdd(&g_M[2], r02);
        atomicAdd(&g_M[3], r11); atomicAdd(&g_M[4], r12); atomicAdd(&g_M[5], r22);
        atomicAdd(&g_fstats[0], fs); atomicAdd(&g_fstats[1], fss);
        atomicMin(&g_mnkey[0], fkey(mn0)); atomicMax(&g_mxkey[0], fkey(mx0));
        atomicMin(&g_mnkey[1], fkey(mn1)); atomicMax(&g_mxkey[1], fkey(mx1));
        atomicMin(&g_mnkey[2], fkey(mn2)); atomicMax(&g_mxkey[2], fkey(mx2));
    }
}

// ---- LAPACK ssyevd-style path in float (validated R14): sytd2('L') -> steqr('I') -> V=Q*Z ----
__device__ void dev_slartg(float f, float g, float* cs, float* sn, float* r) {
    if (g == 0.f) { *cs = 1.f; *sn = 0.f; *r = f; }
    else if (f == 0.f) { *cs = 0.f; *sn = 1.f; *r = g; }
    else {
        float rr = sqrtf(f * f + g * g);
        float c = f / rr, s = g / rr;
        if (fabsf(f) > fabsf(g) && c < 0.f) { c = -c; s = -s; rr = -rr; }
        *cs = c; *sn = s; *r = rr;
    }
}

__device__ void dev_slaev2(float a, float b, float c,
                           float* rt1, float* rt2, float* cs1, float* sn1) {
    float sm = a + c, df = a - c;
    float adf = fabsf(df), tb = b + b, ab = fabsf(tb);
    float acmx, acmn;
    if (fabsf(a) > fabsf(c)) { acmx = a; acmn = c; } else { acmx = c; acmn = a; }
    float rt;
    if (adf > ab) rt = adf * sqrtf(1.f + (ab / adf) * (ab / adf));
    else if (adf < ab) rt = ab * sqrtf(1.f + (adf / ab) * (adf / ab));
    else rt = ab * sqrtf(2.f);
    int sgn1;
    if (sm < 0.f) { *rt1 = 0.5f * (sm - rt); sgn1 = -1; *rt2 = (acmx / *rt1) * acmn - (b / *rt1) * b; }
    else if (sm > 0.f) { *rt1 = 0.5f * (sm + rt); sgn1 = 1; *rt2 = (acmx / *rt1) * acmn - (b / *rt1) * b; }
    else { *rt1 = 0.5f * rt; *rt2 = -0.5f * rt; sgn1 = 1; }
    float cs; int sgn2;
    if (df >= 0.f) { cs = df + rt; sgn2 = 1; } else { cs = df - rt; sgn2 = -1; }
    float acs = fabsf(cs);
    if (acs > ab) {
        float ct = -tb / cs;
        *sn1 = 1.f / sqrtf(1.f + ct * ct);
        *cs1 = ct * (*sn1);
    } else {
        if (ab == 0.f) { *cs1 = 1.f; *sn1 = 0.f; }
        else {
            float tn = -cs / tb;
            *cs1 = 1.f / sqrtf(1.f + tn * tn);
            *sn1 = tn * (*cs1);
        }
    }
    if (sgn1 == sgn2) { float tn = *cs1; *cs1 = -(*sn1); *sn1 = tn; }
}

__global__ void k_eigh(int nn) {
    if (threadIdx.x != 0) return;
    double mu0 = g_psum[0] / (double)nn, mu1 = g_psum[1] / (double)nn, mu2 = g_psum[2] / (double)nn;
    g_pmean[0] = (float)mu0; g_pmean[1] = (float)mu1; g_pmean[2] = (float)mu2;
    {
        double cnt = (double)nn * 32.0;
        double mu = g_fstats[0] / cnt;
        double var = g_fstats[1] / cnt - mu * mu;
        if (var < 0.0) var = 0.0;
        g_fp[0] = (float)mu;
        g_fp[1] = (float)sqrt(var) + 1e-5f;
    }
    double mus[3] = {mu0, mu1, mu2};
    float mxab = 0.f;
    for (int c = 0; c < 3; c++) {
        float hi = funkey(g_mxkey[c]) - (float)mus[c];
        float lo = (float)mus[c] - funkey(g_mnkey[c]);
        mxab = fmaxf(mxab, fmaxf(hi, lo));
    }
    float sc = (1.0f / mxab) * 0.999999f;
    g_pscale = sc;
    double s2d = (double)sc * (double)sc;
    double N = (double)nn;
    float a00 = (float)((g_M[0] - N * mu0 * mu0) * s2d);
    float a01 = (float)((g_M[1] - N * mu0 * mu1) * s2d);
    float a02 = (float)((g_M[2] - N * mu0 * mu2) * s2d);
    float a11 = (float)((g_M[3] - N * mu1 * mu1) * s2d);
    float a12 = (float)((g_M[4] - N * mu1 * mu2) * s2d);
    float a22 = (float)((g_M[5] - N * mu2 * mu2) * s2d);

    float d[4], e[3];
    float tau = 0.f, v1 = 0.f;
    {
        float alpha = a01;
        float x = a02;
        float xnorm = fabsf(x);
        float beta;
        if (xnorm == 0.f) { tau = 0.f; beta = alpha; }
        else {
            float hy = sqrtf(alpha * alpha + xnorm * xnorm);
            beta = (alpha >= 0.f) ? -hy : hy;
            tau = (beta - alpha) / beta;
            v1 = x / (alpha - beta);
        }
        e[1] = beta;
        float nd11 = a11, nd12 = a12, nd22 = a22;
        if (tau != 0.f) {
            float w0 = tau * (a11 + a12 * v1);
            float w1 = tau * (a12 + a22 * v1);
            float al = -0.5f * tau * (w0 + w1 * v1);
            w0 += al;
            w1 += al * v1;
            nd11 = a11 - 2.f * w0;
            nd12 = a12 - (w1 + w0 * v1);
            nd22 = a22 - 2.f * v1 * w1;
        }
        d[1] = a00; d[2] = nd11; d[3] = nd22;
        e[2] = nd12;
    }

    const int n = 3;
    float Z[4][4];
    for (int i = 1; i <= 3; i++)
        for (int j = 1; j <= 3; j++) Z[i][j] = (i == j) ? 1.f : 0.f;
    float eps = 1.1920929e-7f;
    float eps2 = eps * eps;
    float safmin = 1.17549435e-38f;
    int nmaxit = n * 30, jtot = 0;
    float wc[4], ws[4];
    int l1 = 1;
    while (true) {
        if (l1 > n) break;
        if (l1 > 1) e[l1 - 1] = 0.f;
        int m;
        if (l1 <= n - 1) {
            for (m = l1; m <= n - 1; m++) {
                float tst = fabsf(e[m]);
                if (tst == 0.f) break;
                if (tst <= (sqrtf(fabsf(d[m])) * sqrtf(fabsf(d[m + 1]))) * eps) { e[m] = 0.f; break; }
            }
        } else m = n;
        int l = l1, lend = m;
        l1 = m + 1;
        if (lend == l) continue;
        if (fabsf(d[lend]) < fabsf(d[l])) { int t = lend; lend = l; l = t; }
        if (lend > l) {
            while (true) {
                int mm;
                if (l != lend) {
                    for (mm = l; mm <= lend - 1; mm++) {
                        float tst = e[mm] * e[mm];
                        if (tst <= (eps2 * fabsf(d[mm]) * fabsf(d[mm + 1]) + safmin)) break;
                    }
                } else mm = lend;
                m = mm;
                if (m < lend) e[m] = 0.f;
                float p = d[l];
                if (m == l) { d[l] = p; l = l + 1; if (l <= lend) continue; else break; }
                if (m == l + 1) {
                    float rt1, rt2, c, s;
                    dev_slaev2(d[l], e[l], d[l + 1], &rt1, &rt2, &c, &s);
                    for (int i = 1; i <= n; i++) {
                        float temp = Z[i][l + 1];
                        Z[i][l + 1] = c * temp - s * Z[i][l];
                        Z[i][l] = s * temp + c * Z[i][l];
                    }
                    d[l] = rt1; d[l + 1] = rt2; e[l] = 0.f;
                    l = l + 2;
                    if (l <= lend) continue; else break;
                }
                if (jtot == nmaxit) break;
                jtot++;
                float g = (d[l + 1] - p) / (2.f * e[l]);
                float r = sqrtf(g * g + 1.f);
                float sg = (g >= 0.f) ? fabsf(r) : -fabsf(r);
                g = d[m] - p + e[l] / (g + sg);
                float s = 1.f, c = 1.f;
                p = 0.f;
                for (int i = m - 1; i >= l; i--) {
                    float f = s * e[i];
                    float b = c * e[i];
                    dev_slartg(g, f, &c, &s, &r);
                    if (i != m - 1) e[i + 1] = r;
                    g = d[i + 1] - p;
                    r = (d[i] - g) * s + 2.f * c * b;
                    p = s * r;
                    d[i + 1] = g + p;
                    g = c * r - b;
                    wc[i] = c; ws[i] = -s;
                }
                for (int j = m - 1; j >= l; j--) {
                    float cj = wc[j], sj = ws[j];
                    for (int i = 1; i <= n; i++) {
                        float temp = Z[i][j + 1];
                        Z[i][j + 1] = cj * temp - sj * Z[i][j];
                        Z[i][j] = sj * temp + cj * Z[i][j];
                    }
                }
                d[l] = d[l] - p;
                e[l] = g;
            }
        } else {
            while (true) {
                int mm;
                if (l != lend) {
                    for (mm = l; mm >= lend + 1; mm--) {
                        float tst = e[mm - 1] * e[mm - 1];
                        if (tst <= (eps2 * fabsf(d[mm]) * fabsf(d[mm - 1]) + safmin)) break;
                    }
                } else mm = lend;
                m = mm;
                if (m > lend) e[m - 1] = 0.f;
                float p = d[l];
                if (m == l) { d[l] = p; l = l - 1; if (l >= lend) continue; else break; }
                if (m == l - 1) {
                    float rt1, rt2, c, s;
                    dev_slaev2(d[l - 1], e[l - 1], d[l], &rt1, &rt2, &c, &s);
                    for (int i = 1; i <= n; i++) {
                        float temp = Z[i][l];
                        Z[i][l] = c * temp - s * Z[i][l - 1];
                        Z[i][l - 1] = s * temp + c * Z[i][l - 1];
                    }
                    d[l - 1] = rt1; d[l] = rt2; e[l - 1] = 0.f;
                    l = l - 2;
                    if (l >= lend) continue; else break;
                }
                if (jtot == nmaxit) break;
                jtot++;
                float g = (d[l - 1] - p) / (2.f * e[l - 1]);
                float r = sqrtf(g * g + 1.f);
                float sg = (g >= 0.f) ? fabsf(r) : -fabsf(r);
                g = d[m] - p + e[l - 1] / (g + sg);
                float s = 1.f, c = 1.f;
                p = 0.f;
                for (int i = m; i <= l - 1; i++) {
                    float f = s * e[i];
                    float b = c * e[i];
                    dev_slartg(g, f, &c, &s, &r);
                    if (i != m) e[i - 1] = r;
                    g = d[i] - p;
                    r = (d[i + 1] - g) * s + 2.f * c * b;
                    p = s * r;
                    d[i] = g + p;
                    g = c * r - b;
                    wc[i] = c; ws[i] = s;
                }
                for (int j = m; j <= l - 1; j++) {
                    float cj = wc[j], sj = ws[j];
                    for (int i = 1; i <= n; i++) {
                        float temp = Z[i][j + 1];
                        Z[i][j + 1] = cj * temp - sj * Z[i][j];
                        Z[i][j] = sj * temp + cj * Z[i][j];
                    }
                }
                d[l] = d[l] - p;
                e[l - 1] = g;
            }
        }
    }
    for (int ii = 2; ii <= n; ii++) {
        int i = ii - 1, k = i;
        float p = d[i];
        for (int j = ii; j <= n; j++) if (d[j] < p) { k = j; p = d[j]; }
        if (k != i) {
            d[k] = d[i]; d[i] = p;
            for (int rr = 1; rr <= n; rr++) { float t = Z[rr][i]; Z[rr][i] = Z[rr][k]; Z[rr][k] = t; }
        }
    }
    float Q[4][4];
    Q[1][1] = 1.f; Q[1][2] = 0.f; Q[1][3] = 0.f;
    Q[2][1] = 0.f; Q[3][1] = 0.f;
    Q[2][2] = 1.f - tau;
    Q[2][3] = -tau * v1;
    Q[3][2] = -tau * v1;
    Q[3][3] = 1.f - tau * v1 * v1;
    for (int i = 1; i <= 3; i++)
        for (int j = 1; j <= 3; j++) {
            float acc = 0.f;
            for (int k = 1; k <= 3; k++) acc += Q[i][k] * Z[k][j];
            g_V[(i - 1) * 3 + (j - 1)] = acc;
        }
}

__global__ void k_buildx0(const float* __restrict__ d, const float* __restrict__ ln1w,
                          const float* __restrict__ ln1b, int n) {
    int idx = blockIdx.x * blockDim.x + threadIdx.x;
    if (idx >= n * 36) return;
    int node = idx / 36, j = idx % 36;
    float val;
    if (j < 3) {
        float sc = g_pscale;
        float a = (d[node * 35 + 0] - g_pmean[0]) * sc;
        float b = (d[node * 35 + 1] - g_pmean[1]) * sc;
        float c = (d[node * 35 + 2] - g_pmean[2]) * sc;
        val = a * g_V[0 + j] + b * g_V[3 + j] + c * g_V[6 + j];
    } else if (j < 35) {
        val = (d[node * 35 + j] - g_fp[0]) / g_fp[1] * ln1w[j - 3] + ln1b[j - 3];
    } else val = 0.f;
    g_x0[idx] = val;
}

__global__ void k_hist(const int* __restrict__ ei, const int* __restrict__ et, int e) {
    int i = blockIdx.x * blockDim.x + threadIdx.x;
    if (i < e) atomicAdd(&g_count16[ei[e + i] * 16 + et[i]], 1);
}

__global__ void k_scanA(int ntot) {
    __shared__ int ws[8];
    int b = blockIdx.x, tid = threadIdx.x, lane = tid & 31, w = tid >> 5;
    int i = b * 256 + tid;
    int v = (i < ntot) ? g_count16[i] : 0;
    int x = v;
    for (int o = 1; o < 32; o <<= 1) {
        int y = __shfl_up_sync(0xffffffffu, x, o);
        if (lane >= o) x += y;
    }
    if (lane == 31) ws[w] = x;
    __syncthreads();
    if (tid == 0) {
        int run = 0;
        for (int j = 0; j < 8; j++) { int t = ws[j]; ws[j] = run; run += t; }
    }
    __syncthreads();
    int excl = x - v + ws[w];
    if (i < ntot) g_rp16[i] = excl;
    if (tid == 255) g_bsum[b] = excl + v;
}

__global__ void k_scanB(int nb) {
    __shared__ int sd[512];
    __shared__ int s_carry;
    int tid = threadIdx.x;
    if (tid == 0) s_carry = 0;
    __syncthreads();
    for (int b0 = 0; b0 < nb; b0 += 512) {
        int i = b0 + tid;
        int v = (i < nb) ? g_bsum[i] : 0;
        sd[tid] = v;
        __syncthreads();
        for (int o = 1; o < 512; o <<= 1) {
            int tv = (tid >= o) ? sd[tid - o] : 0;
            __syncthreads();
            sd[tid] += tv;
            __syncthreads();
        }
        int c = s_carry;
        if (i < nb) g_boff[i] = c + sd[tid] - v;
        __syncthreads();
        if (tid == 511) s_carry = c + sd[511];
        __syncthreads();
    }
}

__global__ void k_scanC(int ntot, int n, int e) {
    int i = blockIdx.x * blockDim.x + threadIdx.x;
    if (i >= ntot) return;
    int rp = g_rp16[i] + g_boff[i >> 8];
    g_cursor16[i] = rp;
    if ((i & 15) == 0) g_rowptr[i >> 4] = rp;
    if (i == 0) g_rowptr[n] = e;
}

__global__ void k_scatter(const int* __restrict__ ei, const int* __restrict__ et, int e) {
    int i = blockIdx.x * blockDim.x + threadIdx.x;
    if (i >= e) return;
    int r = et[i];
    int pos = atomicAdd(&g_cursor16[ei[e + i] * 16 + r], 1);
    g_epack[pos] = ei[i] | (r << 20);
}

// Tensor-core GEMM: xr[r] = x @ W[r] (fp16 in, fp32 acc), qv/kv fused epilogue.
template <int F, int STRIDE, int KP>
__global__ void k_gemm(const float* __restrict__ W, const float* __restrict__ qvec,
                       const float* __restrict__ kvec, int n) {
    __shared__ __half xs[128][56];
    __shared__ __half wt[32][56];
    __shared__ __half xout[128][36];
    __shared__ float sq[32], sk[32];
    int tid = threadIdx.x;
    int w = tid >> 5, lane = tid & 31, g = lane >> 2, t = lane & 3;
    int base = blockIdx.x * 128;
    const float* xbuf = (F == 35) ? g_x0 : g_x;

    for (int idx = tid; idx < 128 * KP; idx += 128) {
        int nl = idx / KP, f = idx % KP;
        int node = base + nl;
        float v = (f < F && node < n) ? xbuf[(size_t)node * STRIDE + f] : 0.f;
        xs[nl][f] = __float2half(v);
    }
    if (tid < 32) { sq[tid] = qvec[tid]; sk[tid] = kvec[tid]; }

    for (int r = 0; r < RREL; r++) {
        __syncthreads();
        for (int idx = tid; idx < 32 * KP; idx += 128) {
            int o = idx / KP, f = idx % KP;
            wt[o][f] = (f < F) ? __float2half(W[((size_t)r * F + f) * 32 + o]) : __float2half(0.f);
        }
        __syncthreads();
        for (int mt = 0; mt < 2; mt++) {
            int rowbase = w * 32 + mt * 16;
            float qp0 = 0, qp1 = 0, kp0 = 0, kp1 = 0;
            for (int nt = 0; nt < 4; nt++) {
                float d0 = 0, d1 = 0, d2 = 0, d3 = 0;
                #pragma unroll
                for (int ks = 0; ks < KP / 16; ks++) {
                    uint32_t a0 = *(const uint32_t*)&xs[rowbase + g][2 * t + ks * 16];
                    uint32_t a1 = *(const uint32_t*)&xs[rowbase + g + 8][2 * t + ks * 16];
                    uint32_t a2 = *(const uint32_t*)&xs[rowbase + g][2 * t + 8 + ks * 16];
                    uint32_t a3 = *(const uint32_t*)&xs[rowbase + g + 8][2 * t + 8 + ks * 16];
                    uint32_t b0 = *(const uint32_t*)&wt[nt * 8 + g][2 * t + ks * 16];
                    uint32_t b1 = *(const uint32_t*)&wt[nt * 8 + g][2 * t + 8 + ks * 16];
                    mma16816(d0, d1, d2, d3, a0, a1, a2, a3, b0, b1);
                }
                int c = nt * 8 + 2 * t;
                *(__half2*)&xout[rowbase + g][c] = __floats2half2_rn(d0, d1);
                *(__half2*)&xout[rowbase + g + 8][c] = __floats2half2_rn(d2, d3);
                qp0 += d0 * sq[c] + d1 * sq[c + 1];
                qp1 += d2 * sq[c] + d3 * sq[c + 1];
                kp0 += d0 * sk[c] + d1 * sk[c + 1];
                kp1 += d2 * sk[c] + d3 * sk[c + 1];
            }
            qp0 += __shfl_xor_sync(0xffffffffu, qp0, 1); qp0 += __shfl_xor_sync(0xffffffffu, qp0, 2);
            qp1 += __shfl_xor_sync(0xffffffffu, qp1, 1); qp1 += __shfl_xor_sync(0xffffffffu, qp1, 2);
            kp0 += __shfl_xor_sync(0xffffffffu, kp0, 1); kp0 += __shfl_xor_sync(0xffffffffu, kp0, 2);
            kp1 += __shfl_xor_sync(0xffffffffu, kp1, 1); kp1 += __shfl_xor_sync(0xffffffffu, kp1, 2);
            if (t == 0) {
                int n0 = base + rowbase + g, n1 = n0 + 8;
                if (n0 < n) { g_qv[n0 * 16 + r] = qp0; g_kv[n0 * 16 + r] = kp0; }
                if (n1 < n) { g_qv[n1 * 16 + r] = qp1; g_kv[n1 * 16 + r] = kp1; }
            }
        }
        __syncwarp();
        #pragma unroll
        for (int i = 0; i < 16; i++) {
            int rl = w * 32 + 2 * i + (lane >> 4);
            int node = base + rl;
            if (node < n) {
                uint32_t v = *(const uint32_t*)&xout[rl][(lane & 15) * 2];
                *(uint32_t*)&g_xr[((size_t)r * n + node) * 32 + (lane & 15) * 2] = v;
            }
        }
    }
}

// ONE-PASS edge kernel (R11 exact): deferred softmax normalization, fused logit+gather.
__global__ void k_edge(const float* __restrict__ bias, int layer, int n) {
    int warp = threadIdx.x >> 5, lane = threadIdx.x & 31;
    int node = blockIdx.x * 8 + warp;
    float h = 0.f;
    bool active = node < n;
    __shared__ float sh_qv[8][16];
    __shared__ float sh_h[8][32];
    if (active && lane < 16) sh_qv[warp][lane] = g_qv[node * 16 + lane];
    __syncwarp();
    if (active) {
        int beg = g_rowptr[node], end = g_rowptr[node + 1];
        float res = (layer > 0) ? g_x[(size_t)node * 32 + lane] : 0.f;
        if (end > beg) {
            int fq = lane & 3, eg = lane >> 2;
            float s = 0.f;
            float acc[8];
            #pragma unroll
            for (int j = 0; j < 8; j++) acc[j] = 0.f;
            for (int cb = beg; cb < end; cb += 32) {
                int i = cb + lane;
                float ee = 0.f;
                int ofs = 0;
                if (i < end) {
                    int p = g_epack[i];
                    int r = p >> 20, src = p & 0xFFFFF;
                    float a = sh_qv[warp][r] + g_kv[src * 16 + r];
                    a = (a > 0.f) ? a : 0.2f * a;
                    ee = __expf(a);
                    ofs = (r * n + src) * 32;
                }
                s += ee;
                int cnt = min(32, end - cb);
                for (int jb = 0; jb < cnt; jb += 8) {
                    int sl = jb + eg;
                    float pw = __shfl_sync(0xffffffffu, ee, sl & 31);
                    int of = __shfl_sync(0xffffffffu, ofs, sl & 31);
                    if (sl >= cnt) pw = 0.f;
                    uint4 v = *(const uint4*)&g_xr[(size_t)of + fq * 8];
                    float2 f0 = __half22float2(*(__half2*)&v.x);
                    float2 f1 = __half22float2(*(__half2*)&v.y);
                    float2 f2 = __half22float2(*(__half2*)&v.z);
                    float2 f3 = __half22float2(*(__half2*)&v.w);
                    acc[0] += pw * f0.x; acc[1] += pw * f0.y;
                    acc[2] += pw * f1.x; acc[3] += pw * f1.y;
                    acc[4] += pw * f2.x; acc[5] += pw * f2.y;
                    acc[6] += pw * f3.x; acc[7] += pw * f3.y;
                }
            }
            s = warpSumF(s);
            float inv = __fdividef(1.f, s + 1e-16f);
            #pragma unroll
            for (int j = 0; j < 8; j++) {
                acc[j] += __shfl_xor_sync(0xffffffffu, acc[j], 4);
                acc[j] += __shfl_xor_sync(0xffffffffu, acc[j], 8);
                acc[j] += __shfl_xor_sync(0xffffffffu, acc[j], 16);
            }
            if (eg == 0) {
                #pragma unroll
                for (int j = 0; j < 8; j++) sh_h[warp][fq * 8 + j] = acc[j] * inv;
            }
            __syncwarp();
            h = sh_h[warp][lane];
        }
        h += bias[lane] + res;
        g_h[(size_t)node * 32 + lane] = h;
    }
    double v = active ? (double)h : 0.0;
    double v2 = active ? (double)h * (double)h : 0.0;
    v = warpSumD(v); v2 = warpSumD(v2);
    __shared__ double sh[2][8];
    if (lane == 0) { sh[0][warp] = v; sh[1][warp] = v2; }
    __syncthreads();
    if (threadIdx.x == 0) {
        double a = 0, b = 0;
        for (int ww = 0; ww < 8; ww++) { a += sh[0][ww]; b += sh[1][ww]; }
        atomicAdd(&g_stats[layer][0], a);
        atomicAdd(&g_stats[layer][1], b);
    }
}

__global__ void k_lnact(const float* __restrict__ lnw, const float* __restrict__ lnb,
                        int layer, int n, int dopool) {
    __shared__ float s_mu, s_std;
    if (threadIdx.x == 0) {
        double cnt = (double)n * 32.0;
        double mu = g_stats[layer][0] / cnt;
        double var = g_stats[layer][1] / cnt - mu * mu;
        if (var < 0.0) var = 0.0;
        s_mu = (float)mu;
        s_std = (float)sqrt(var) + 1e-5f;
    }
    __syncthreads();
    float mu = s_mu, stdpe = s_std;
    int f = threadIdx.x & 31;
    float w = lnw[f], b = lnb[f];
    double acc = 0.0;
    int total = n * 32;
    for (int i = blockIdx.x * blockDim.x + threadIdx.x; i < total; i += gridDim.x * blockDim.x) {
        float t = (g_h[i] - mu) / stdpe * w + b;
        float sig = 1.f / (1.f + __expf(-t));
        float xo = t * sig;
        g_x[i] = xo;
        acc += (double)xo;
    }
    if (dopool) {
        __shared__ double shd[8][32];
        int warp = threadIdx.x >> 5;
        shd[warp][f] = acc;
        __syncthreads();
        if (warp == 0) {
            double a = 0;
            for (int ww = 0; ww < 8; ww++) a += shd[ww][f];
            atomicAdd(&g_pool[f], a);
        }
    }
}

__global__ void k_final(const float* __restrict__ W, const float* __restrict__ b,
                        float* __restrict__ out, int n) {
    __shared__ float x3[32];
    if (threadIdx.x < 32) x3[threadIdx.x] = (float)(g_pool[threadIdx.x] / (double)n);
    __syncthreads();
    int j = threadIdx.x;
    if (j < 256) {
        float acc = b[j];
        #pragma unroll
        for (int o = 0; o < 32; o++) acc += x3[o] * W[j * 32 + o];
        float sig = 1.f / (1.f + expf(-acc));
        out[j] = acc * sig;
    }
}

extern "C" void kernel_launch(void* const* d_in, const int* in_sizes, int n_in,
                              void* d_out, int out_size) {
    const float* db1  = (const float*)d_in[0];
    const int*   ei   = (const int*)d_in[2];
    const int*   et   = (const int*)d_in[3];
    const float* W0   = (const float*)d_in[6];
    const float* q0   = (const float*)d_in[7];
    const float* k0   = (const float*)d_in[8];
    const float* b0   = (const float*)d_in[9];
    const float* Ws   = (const float*)d_in[10];
    const float* qs   = (const float*)d_in[11];
    const float* ks   = (const float*)d_in[12];
    const float* bs   = (const float*)d_in[13];
    const float* lnw  = (const float*)d_in[14];
    const float* lnb  = (const float*)d_in[15];
    const float* ln1w = (const float*)d_in[16];
    const float* ln1b = (const float*)d_in[17];
    const float* l1W  = (const float*)d_in[18];
    const float* l1b  = (const float*)d_in[19];
    float* out = (float*)d_out;
    int n = in_sizes[0] / 35;
    int e = in_sizes[3];
    int ntot = n * 16;
    int nb16 = (ntot + 255) / 256;

    k_zero<<<512, 256>>>();
    k_stats<<<512, 256>>>(db1, n);
    k_eigh<<<1, 1>>>(n);
    k_buildx0<<<(n * 36 + 255) / 256, 256>>>(db1, ln1w, ln1b, n);

    k_hist<<<(e + 255) / 256, 256>>>(ei, et, e);
    k_scanA<<<nb16, 256>>>(ntot);
    k_scanB<<<1, 512>>>(nb16);
    k_scanC<<<nb16, 256>>>(ntot, n, e);
    k_scatter<<<(e + 255) / 256, 256>>>(ei, et, e);

    int gg = (n + 127) / 128;
    for (int l = 0; l < NLAY; l++) {
        const float* bias = (l == 0) ? b0 : bs + (l - 1) * 32;
        if (l == 0) {
            k_gemm<35, 36, 48><<<gg, 128>>>(W0, q0, k0, n);
        } else {
            k_gemm<32, 32, 32><<<gg, 128>>>(Ws + (size_t)(l - 1) * RREL * 32 * 32,
                                            qs + (l - 1) * 32, ks + (l - 1) * 32, n);
        }
        k_edge<<<(n + 7) / 8, 256>>>(bias, l, n);
        k_lnact<<<512, 256>>>(lnw + l * 32, lnb + l * 32, l, n, (l == NLAY - 1) ? 1 : 0);
    }
    k_final<<<1, 256>>>(l1W, l1b, out, n);
}

// round 17
// speedup vs baseline: 1.3778x; 1.2022x over previous
#include <cuda_runtime.h>
#include <cuda_fp16.h>
#include <math.h>
#include <stdint.h>

#define NMAX 100000
#define EMAX 3200000
#define RREL 15
#define NLAY 4
#define NB16 (NMAX * 16)

__device__ __half g_xr[(size_t)RREL * NMAX * 32];
__device__ float g_x0[NMAX * 36];
__device__ float g_x[NMAX * 32];
__device__ float g_h[NMAX * 32];
__device__ float g_qv[NMAX * 16];
__device__ float g_kv[NMAX * 16];
__device__ int   g_rowptr[NMAX + 1];
__device__ int   g_cursor16[NB16];
__device__ int   g_count16[NB16];
__device__ int   g_rp16[NB16];
__device__ int   g_epack[EMAX];
__device__ int   g_bsum[6400];
__device__ int   g_boff[6400];
__device__ double g_stats[NLAY][2];
__device__ double g_pool[32];
__device__ double g_psum[3];
__device__ double g_M[6];
__device__ unsigned int g_mnkey[3], g_mxkey[3];
__device__ float  g_pmean[3];
__device__ float g_V[9];
__device__ float g_pscale;
__device__ double g_fstats[2];
__device__ float  g_fp[2];

__device__ __forceinline__ double warpSumD(double v) {
    for (int o = 16; o > 0; o >>= 1) v += __shfl_down_sync(0xffffffffu, v, o);
    return v;
}
__device__ __forceinline__ float warpSumF(float v) {
    for (int o = 16; o > 0; o >>= 1) v += __shfl_xor_sync(0xffffffffu, v, o);
    return v;
}
__device__ __forceinline__ unsigned int fkey(float f) {
    unsigned int u = __float_as_uint(f);
    return (u & 0x80000000u) ? ~u : (u | 0x80000000u);
}
__device__ __forceinline__ float funkey(unsigned int k) {
    return (k & 0x80000000u) ? __uint_as_float(k ^ 0x80000000u) : __uint_as_float(~k);
}

__device__ __forceinline__ void mma16816(float& d0, float& d1, float& d2, float& d3,
    uint32_t a0, uint32_t a1, uint32_t a2, uint32_t a3, uint32_t b0, uint32_t b1) {
    asm volatile("mma.sync.aligned.m16n8k16.row.col.f32.f16.f16.f32 "
        "{%0,%1,%2,%3}, {%4,%5,%6,%7}, {%8,%9}, {%0,%1,%2,%3};"
        : "+f"(d0), "+f"(d1), "+f"(d2), "+f"(d3)
        : "r"(a0), "r"(a1), "r"(a2), "r"(a3), "r"(b0), "r"(b1));
}

__global__ void k_zero() {
    int i = blockIdx.x * blockDim.x + threadIdx.x;
    int stride = gridDim.x * blockDim.x;
    for (int j = i; j < NB16; j += stride) g_count16[j] = 0;
    if (i == 0) {
        for (int l = 0; l < NLAY; l++) { g_stats[l][0] = 0.0; g_stats[l][1] = 0.0; }
        for (int o = 0; o < 32; o++) g_pool[o] = 0.0;
        for (int c = 0; c < 3; c++) { g_psum[c] = 0.0; g_mnkey[c] = 0xFFFFFFFFu; g_mxkey[c] = 0u; }
        for (int c = 0; c < 6; c++) g_M[c] = 0.0;
        g_fstats[0] = 0.0; g_fstats[1] = 0.0;
    }
}

__global__ void k_stats(const float* __restrict__ d, int n) {
    int gtid = blockIdx.x * blockDim.x + threadIdx.x;
    int stride = gridDim.x * blockDim.x;
    double s0 = 0, s1 = 0, s2 = 0;
    double r00 = 0, r01 = 0, r02 = 0, r11 = 0, r12 = 0, r22 = 0;
    float mn0 = 3e38f, mn1 = 3e38f, mn2 = 3e38f;
    float mx0 = -3e38f, mx1 = -3e38f, mx2 = -3e38f;
    for (int i = gtid; i < n; i += stride) {
        float x = d[i * 35 + 0], y = d[i * 35 + 1], z = d[i * 35 + 2];
        double dx = x, dy = y, dz = z;
        s0 += dx; s1 += dy; s2 += dz;
        r00 += dx * dx; r01 += dx * dy; r02 += dx * dz;
        r11 += dy * dy; r12 += dy * dz; r22 += dz * dz;
        mn0 = fminf(mn0, x); mx0 = fmaxf(mx0, x);
        mn1 = fminf(mn1, y); mx1 = fmaxf(mx1, y);
        mn2 = fminf(mn2, z); mx2 = fmaxf(mx2, z);
    }
    double fs = 0, fss = 0;
    int total = n * 35;
    int q4 = total >> 2;
    const float4* d4 = (const float4*)d;
    for (int j = gtid; j < q4; j += stride) {
        float4 v = d4[j];
        int idx = j * 4;
        int c = idx - (idx / 35) * 35;
        if (c >= 3) { double t = v.x; fs += t; fss += t * t; }
        c = (c == 34) ? 0 : c + 1;
        if (c >= 3) { double t = v.y; fs += t; fss += t * t; }
        c = (c == 34) ? 0 : c + 1;
        if (c >= 3) { double t = v.z; fs += t; fss += t * t; }
        c = (c == 34) ? 0 : c + 1;
        if (c >= 3) { double t = v.w; fs += t; fss += t * t; }
    }
    if (gtid == 0) {
        for (int idx = q4 * 4; idx < total; idx++) {
            int c = idx - (idx / 35) * 35;
            if (c >= 3) { double t = d[idx]; fs += t; fss += t * t; }
        }
    }
    s0 = warpSumD(s0); s1 = warpSumD(s1); s2 = warpSumD(s2);
    r00 = warpSumD(r00); r01 = warpSumD(r01); r02 = warpSumD(r02);
    r11 = warpSumD(r11); r12 = warpSumD(r12); r22 = warpSumD(r22);
    fs = warpSumD(fs); fss = warpSumD(fss);
    for (int o = 16; o > 0; o >>= 1) {
        mn0 = fminf(mn0, __shfl_down_sync(0xffffffffu, mn0, o));
        mn1 = fminf(mn1, __shfl_down_sync(0xffffffffu, mn1, o));
        mn2 = fminf(mn2, __shfl_down_sync(0xffffffffu, mn2, o));
        mx0 = fmaxf(mx0, __shfl_down_sync(0xffffffffu, mx0, o));
        mx1 = fmaxf(mx1, __shfl_down_sync(0xffffffffu, mx1, o));
        mx2 = fmaxf(mx2, __shfl_down_sync(0xffffffffu, mx2, o));
    }
    if ((threadIdx.x & 31) == 0) {
        atomicAdd(&g_psum[0], s0); atomicAdd(&g_psum[1], s1); atomicAdd(&g_psum[2], s2);
        atomicAdd(&g_M[0], r00); atomicAdd(&g_M[1], r01); atomicAdd(&g_M[2], r02);
        atomicAdd(&g_M[3], r11); atomicAdd(&g_M[4], r12); atomicAdd(&g_M[5], r22);
        atomicAdd(&g_fstats[0], fs); atomicAdd(&g_fstats[1], fss);
        atomicMin(&g_mnkey[0], fkey(mn0)); atomicMax(&g_mxkey[0], fkey(mx0));
        atomicMin(&g_mnkey[1], fkey(mn1)); atomicMax(&g_mxkey[1], fkey(mx1));
        atomicMin(&g_mnkey[2], fkey(mn2)); atomicMax(&g_mxkey[2], fkey(mx2));
    }
}

// ---- LAPACK ssyevd-style path in float (validated R14/R15) ----
__device__ void dev_slartg(float f, float g, float* cs, float* sn, float* r) {
    if (g == 0.f) { *cs = 1.f; *sn = 0.f; *r = f; }
    else if (f == 0.f) { *cs = 0.f; *sn = 1.f; *r = g; }
    else {
        float rr = sqrtf(f * f + g * g);
        float c = f / rr, s = g / rr;
        if (fabsf(f) > fabsf(g) && c < 0.f) { c = -c; s = -s; rr = -rr; }
        *cs = c; *sn = s; *r = rr;
    }
}

__device__ void dev_slaev2(float a, float b, float c,
                           float* rt1, float* rt2, float* cs1, float* sn1) {
    float sm = a + c, df = a - c;
    float adf = fabsf(df), tb = b + b, ab = fabsf(tb);
    float acmx, acmn;
    if (fabsf(a) > fabsf(c)) { acmx = a; acmn = c; } else { acmx = c; acmn = a; }
    float rt;
    if (adf > ab) rt = adf * sqrtf(1.f + (ab / adf) * (ab / adf));
    else if (adf < ab) rt = ab * sqrtf(1.f + (adf / ab) * (adf / ab));
    else rt = ab * sqrtf(2.f);
    int sgn1;
    if (sm < 0.f) { *rt1 = 0.5f * (sm - rt); sgn1 = -1; *rt2 = (acmx / *rt1) * acmn - (b / *rt1) * b; }
    else if (sm > 0.f) { *rt1 = 0.5f * (sm + rt); sgn1 = 1; *rt2 = (acmx / *rt1) * acmn - (b / *rt1) * b; }
    else { *rt1 = 0.5f * rt; *rt2 = -0.5f * rt; sgn1 = 1; }
    float cs; int sgn2;
    if (df >= 0.f) { cs = df + rt; sgn2 = 1; } else { cs = df - rt; sgn2 = -1; }
    float acs = fabsf(cs);
    if (acs > ab) {
        float ct = -tb / cs;
        *sn1 = 1.f / sqrtf(1.f + ct * ct);
        *cs1 = ct * (*sn1);
    } else {
        if (ab == 0.f) { *cs1 = 1.f; *sn1 = 0.f; }
        else {
            float tn = -cs / tb;
            *cs1 = 1.f / sqrtf(1.f + tn * tn);
            *sn1 = tn * (*cs1);
        }
    }
    if (sgn1 == sgn2) { float tn = *cs1; *cs1 = -(*sn1); *sn1 = tn; }
}

__global__ void k_eigh(int nn) {
    if (threadIdx.x != 0) return;
    double mu0 = g_psum[0] / (double)nn, mu1 = g_psum[1] / (double)nn, mu2 = g_psum[2] / (double)nn;
    g_pmean[0] = (float)mu0; g_pmean[1] = (float)mu1; g_pmean[2] = (float)mu2;
    {
        double cnt = (double)nn * 32.0;
        double mu = g_fstats[0] / cnt;
        double var = g_fstats[1] / cnt - mu * mu;
        if (var < 0.0) var = 0.0;
        g_fp[0] = (float)mu;
        g_fp[1] = (float)sqrt(var) + 1e-5f;
    }
    double mus[3] = {mu0, mu1, mu2};
    float mxab = 0.f;
    for (int c = 0; c < 3; c++) {
        float hi = funkey(g_mxkey[c]) - (float)mus[c];
        float lo = (float)mus[c] - funkey(g_mnkey[c]);
        mxab = fmaxf(mxab, fmaxf(hi, lo));
    }
    float sc = (1.0f / mxab) * 0.999999f;
    g_pscale = sc;
    double s2d = (double)sc * (double)sc;
    double N = (double)nn;
    float a00 = (float)((g_M[0] - N * mu0 * mu0) * s2d);
    float a01 = (float)((g_M[1] - N * mu0 * mu1) * s2d);
    float a02 = (float)((g_M[2] - N * mu0 * mu2) * s2d);
    float a11 = (float)((g_M[3] - N * mu1 * mu1) * s2d);
    float a12 = (float)((g_M[4] - N * mu1 * mu2) * s2d);
    float a22 = (float)((g_M[5] - N * mu2 * mu2) * s2d);

    float d[4], e[3];
    float tau = 0.f, v1 = 0.f;
    {
        float alpha = a01;
        float x = a02;
        float xnorm = fabsf(x);
        float beta;
        if (xnorm == 0.f) { tau = 0.f; beta = alpha; }
        else {
            float hy = sqrtf(alpha * alpha + xnorm * xnorm);
            beta = (alpha >= 0.f) ? -hy : hy;
            tau = (beta - alpha) / beta;
            v1 = x / (alpha - beta);
        }
        e[1] = beta;
        float nd11 = a11, nd12 = a12, nd22 = a22;
        if (tau != 0.f) {
            float w0 = tau * (a11 + a12 * v1);
            float w1 = tau * (a12 + a22 * v1);
            float al = -0.5f * tau * (w0 + w1 * v1);
            w0 += al;
            w1 += al * v1;
            nd11 = a11 - 2.f * w0;
            nd12 = a12 - (w1 + w0 * v1);
            nd22 = a22 - 2.f * v1 * w1;
        }
        d[1] = a00; d[2] = nd11; d[3] = nd22;
        e[2] = nd12;
    }

    const int n = 3;
    float Z[4][4];
    for (int i = 1; i <= 3; i++)
        for (int j = 1; j <= 3; j++) Z[i][j] = (i == j) ? 1.f : 0.f;
    float eps = 1.1920929e-7f;
    float eps2 = eps * eps;
    float safmin = 1.17549435e-38f;
    int nmaxit = n * 30, jtot = 0;
    float wc[4], ws[4];
    int l1 = 1;
    while (true) {
        if (l1 > n) break;
        if (l1 > 1) e[l1 - 1] = 0.f;
        int m;
        if (l1 <= n - 1) {
            for (m = l1; m <= n - 1; m++) {
                float tst = fabsf(e[m]);
                if (tst == 0.f) break;
                if (tst <= (sqrtf(fabsf(d[m])) * sqrtf(fabsf(d[m + 1]))) * eps) { e[m] = 0.f; break; }
            }
        } else m = n;
        int l = l1, lend = m;
        l1 = m + 1;
        if (lend == l) continue;
        if (fabsf(d[lend]) < fabsf(d[l])) { int t = lend; lend = l; l = t; }
        if (lend > l) {
            while (true) {
                int mm;
                if (l != lend) {
                    for (mm = l; mm <= lend - 1; mm++) {
                        float tst = e[mm] * e[mm];
                        if (tst <= (eps2 * fabsf(d[mm]) * fabsf(d[mm + 1]) + safmin)) break;
                    }
                } else mm = lend;
                m = mm;
                if (m < lend) e[m] = 0.f;
                float p = d[l];
                if (m == l) { d[l] = p; l = l + 1; if (l <= lend) continue; else break; }
                if (m == l + 1) {
                    float rt1, rt2, c, s;
                    dev_slaev2(d[l], e[l], d[l + 1], &rt1, &rt2, &c, &s);
                    for (int i = 1; i <= n; i++) {
                        float temp = Z[i][l + 1];
                        Z[i][l + 1] = c * temp - s * Z[i][l];
                        Z[i][l] = s * temp + c * Z[i][l];
                    }
                    d[l] = rt1; d[l + 1] = rt2; e[l] = 0.f;
                    l = l + 2;
                    if (l <= lend) continue; else break;
                }
                if (jtot == nmaxit) break;
                jtot++;
                float g = (d[l + 1] - p) / (2.f * e[l]);
                float r = sqrtf(g * g + 1.f);
                float sg = (g >= 0.f) ? fabsf(r) : -fabsf(r);
                g = d[m] - p + e[l] / (g + sg);
                float s = 1.f, c = 1.f;
                p = 0.f;
                for (int i = m - 1; i >= l; i--) {
                    float f = s * e[i];
                    float b = c * e[i];
                    dev_slartg(g, f, &c, &s, &r);
                    if (i != m - 1) e[i + 1] = r;
                    g = d[i + 1] - p;
                    r = (d[i] - g) * s + 2.f * c * b;
                    p = s * r;
                    d[i + 1] = g + p;
                    g = c * r - b;
                    wc[i] = c; ws[i] = -s;
                }
                for (int j = m - 1; j >= l; j--) {
                    float cj = wc[j], sj = ws[j];
                    for (int i = 1; i <= n; i++) {
                        float temp = Z[i][j + 1];
                        Z[i][j + 1] = cj * temp - sj * Z[i][j];
                        Z[i][j] = sj * temp + cj * Z[i][j];
                    }
                }
                d[l] = d[l] - p;
                e[l] = g;
            }
        } else {
            while (true) {
                int mm;
                if (l != lend) {
                    for (mm = l; mm >= lend + 1; mm--) {
                        float tst = e[mm - 1] * e[mm - 1];
                        if (tst <= (eps2 * fabsf(d[mm]) * fabsf(d[mm - 1]) + safmin)) break;
                    }
                } else mm = lend;
                m = mm;
                if (m > lend) e[m - 1] = 0.f;
                float p = d[l];
                if (m == l) { d[l] = p; l = l - 1; if (l >= lend) continue; else break; }
                if (m == l - 1) {
                    float rt1, rt2, c, s;
                    dev_slaev2(d[l - 1], e[l - 1], d[l], &rt1, &rt2, &c, &s);
                    for (int i = 1; i <= n; i++) {
                        float temp = Z[i][l];
                        Z[i][l] = c * temp - s * Z[i][l - 1];
                        Z[i][l - 1] = s * temp + c * Z[i][l - 1];
                    }
                    d[l - 1] = rt1; d[l] = rt2; e[l - 1] = 0.f;
                    l = l - 2;
                    if (l >= lend) continue; else break;
                }
                if (jtot == nmaxit) break;
                jtot++;
                float g = (d[l - 1] - p) / (2.f * e[l - 1]);
                float r = sqrtf(g * g + 1.f);
                float sg = (g >= 0.f) ? fabsf(r) : -fabsf(r);
                g = d[m] - p + e[l - 1] / (g + sg);
                float s = 1.f, c = 1.f;
                p = 0.f;
                for (int i = m; i <= l - 1; i++) {
                    float f = s * e[i];
                    float b = c * e[i];
                    dev_slartg(g, f, &c, &s, &r);
                    if (i != m) e[i - 1] = r;
                    g = d[i] - p;
                    r = (d[i + 1] - g) * s + 2.f * c * b;
                    p = s * r;
                    d[i] = g + p;
                    g = c * r - b;
                    wc[i] = c; ws[i] = s;
                }
                for (int j = m; j <= l - 1; j++) {
                    float cj = wc[j], sj = ws[j];
                    for (int i = 1; i <= n; i++) {
                        float temp = Z[i][j + 1];
                        Z[i][j + 1] = cj * temp - sj * Z[i][j];
                        Z[i][j] = sj * temp + cj * Z[i][j];
                    }
                }
                d[l] = d[l] - p;
                e[l - 1] = g;
            }
        }
    }
    for (int ii = 2; ii <= n; ii++) {
        int i = ii - 1, k = i;
        float p = d[i];
        for (int j = ii; j <= n; j++) if (d[j] < p) { k = j; p = d[j]; }
        if (k != i) {
            d[k] = d[i]; d[i] = p;
            for (int rr = 1; rr <= n; rr++) { float t = Z[rr][i]; Z[rr][i] = Z[rr][k]; Z[rr][k] = t; }
        }
    }
    float Q[4][4];
    Q[1][1] = 1.f; Q[1][2] = 0.f; Q[1][3] = 0.f;
    Q[2][1] = 0.f; Q[3][1] = 0.f;
    Q[2][2] = 1.f - tau;
    Q[2][3] = -tau * v1;
    Q[3][2] = -tau * v1;
    Q[3][3] = 1.f - tau * v1 * v1;
    for (int i = 1; i <= 3; i++)
        for (int j = 1; j <= 3; j++) {
            float acc = 0.f;
            for (int k = 1; k <= 3; k++) acc += Q[i][k] * Z[k][j];
            g_V[(i - 1) * 3 + (j - 1)] = acc;
        }
}

__global__ void k_buildx0(const float* __restrict__ d, const float* __restrict__ ln1w,
                          const float* __restrict__ ln1b, int n) {
    int idx = blockIdx.x * blockDim.x + threadIdx.x;
    if (idx >= n * 36) return;
    int node = idx / 36, j = idx % 36;
    float val;
    if (j < 3) {
        float sc = g_pscale;
        float a = (d[node * 35 + 0] - g_pmean[0]) * sc;
        float b = (d[node * 35 + 1] - g_pmean[1]) * sc;
        float c = (d[node * 35 + 2] - g_pmean[2]) * sc;
        val = a * g_V[0 + j] + b * g_V[3 + j] + c * g_V[6 + j];
    } else if (j < 35) {
        val = (d[node * 35 + j] - g_fp[0]) / g_fp[1] * ln1w[j - 3] + ln1b[j - 3];
    } else val = 0.f;
    g_x0[idx] = val;
}

__global__ void k_hist(const int* __restrict__ ei, const int* __restrict__ et, int e) {
    int i = blockIdx.x * blockDim.x + threadIdx.x;
    if (i < e) atomicAdd(&g_count16[ei[e + i] * 16 + et[i]], 1);
}

__global__ void k_scanA(int ntot) {
    __shared__ int ws[8];
    int b = blockIdx.x, tid = threadIdx.x, lane = tid & 31, w = tid >> 5;
    int i = b * 256 + tid;
    int v = (i < ntot) ? g_count16[i] : 0;
    int x = v;
    for (int o = 1; o < 32; o <<= 1) {
        int y = __shfl_up_sync(0xffffffffu, x, o);
        if (lane >= o) x += y;
    }
    if (lane == 31) ws[w] = x;
    __syncthreads();
    if (tid == 0) {
        int run = 0;
        for (int j = 0; j < 8; j++) { int t = ws[j]; ws[j] = run; run += t; }
    }
    __syncthreads();
    int excl = x - v + ws[w];
    if (i < ntot) g_rp16[i] = excl;
    if (tid == 255) g_bsum[b] = excl + v;
}

__global__ void k_scanB(int nb) {
    __shared__ int sd[512];
    __shared__ int s_carry;
    int tid = threadIdx.x;
    if (tid == 0) s_carry = 0;
    __syncthreads();
    for (int b0 = 0; b0 < nb; b0 += 512) {
        int i = b0 + tid;
        int v = (i < nb) ? g_bsum[i] : 0;
        sd[tid] = v;
        __syncthreads();
        for (int o = 1; o < 512; o <<= 1) {
            int tv = (tid >= o) ? sd[tid - o] : 0;
            __syncthreads();
            sd[tid] += tv;
            __syncthreads();
        }
        int c = s_carry;
        if (i < nb) g_boff[i] = c + sd[tid] - v;
        __syncthreads();
        if (tid == 511) s_carry = c + sd[511];
        __syncthreads();
    }
}

__global__ void k_scanC(int ntot, int n, int e) {
    int i = blockIdx.x * blockDim.x + threadIdx.x;
    if (i >= ntot) return;
    int rp = g_rp16[i] + g_boff[i >> 8];
    g_cursor16[i] = rp;
    if ((i & 15) == 0) g_rowptr[i >> 4] = rp;
    if (i == 0) g_rowptr[n] = e;
}

__global__ void k_scatter(const int* __restrict__ ei, const int* __restrict__ et, int e) {
    int i = blockIdx.x * blockDim.x + threadIdx.x;
    if (i >= e) return;
    int r = et[i];
    int pos = atomicAdd(&g_cursor16[ei[e + i] * 16 + r], 1);
    g_epack[pos] = ei[i] | (r << 20);
}

// Tensor-core GEMM: xr[r] = x @ W[r] (fp16 in, fp32 acc), qv/kv fused epilogue.
template <int F, int STRIDE, int KP>
__global__ void k_gemm(const float* __restrict__ W, const float* __restrict__ qvec,
                       const float* __restrict__ kvec, int n) {
    __shared__ __half xs[128][56];
    __shared__ __half wt[32][56];
    __shared__ __half xout[128][36];
    __shared__ float sq[32], sk[32];
    int tid = threadIdx.x;
    int w = tid >> 5, lane = tid & 31, g = lane >> 2, t = lane & 3;
    int base = blockIdx.x * 128;
    const float* xbuf = (F == 35) ? g_x0 : g_x;

    for (int idx = tid; idx < 128 * KP; idx += 128) {
        int nl = idx / KP, f = idx % KP;
        int node = base + nl;
        float v = (f < F && node < n) ? xbuf[(size_t)node * STRIDE + f] : 0.f;
        xs[nl][f] = __float2half(v);
    }
    if (tid < 32) { sq[tid] = qvec[tid]; sk[tid] = kvec[tid]; }

    for (int r = 0; r < RREL; r++) {
        __syncthreads();
        for (int idx = tid; idx < 32 * KP; idx += 128) {
            int o = idx / KP, f = idx % KP;
            wt[o][f] = (f < F) ? __float2half(W[((size_t)r * F + f) * 32 + o]) : __float2half(0.f);
        }
        __syncthreads();
        for (int mt = 0; mt < 2; mt++) {
            int rowbase = w * 32 + mt * 16;
            float qp0 = 0, qp1 = 0, kp0 = 0, kp1 = 0;
            for (int nt = 0; nt < 4; nt++) {
                float d0 = 0, d1 = 0, d2 = 0, d3 = 0;
                #pragma unroll
                for (int ks = 0; ks < KP / 16; ks++) {
                    uint32_t a0 = *(const uint32_t*)&xs[rowbase + g][2 * t + ks * 16];
                    uint32_t a1 = *(const uint32_t*)&xs[rowbase + g + 8][2 * t + ks * 16];
                    uint32_t a2 = *(const uint32_t*)&xs[rowbase + g][2 * t + 8 + ks * 16];
                    uint32_t a3 = *(const uint32_t*)&xs[rowbase + g + 8][2 * t + 8 + ks * 16];
                    uint32_t b0 = *(const uint32_t*)&wt[nt * 8 + g][2 * t + ks * 16];
                    uint32_t b1 = *(const uint32_t*)&wt[nt * 8 + g][2 * t + 8 + ks * 16];
                    mma16816(d0, d1, d2, d3, a0, a1, a2, a3, b0, b1);
                }
                int c = nt * 8 + 2 * t;
                *(__half2*)&xout[rowbase + g][c] = __floats2half2_rn(d0, d1);
                *(__half2*)&xout[rowbase + g + 8][c] = __floats2half2_rn(d2, d3);
                qp0 += d0 * sq[c] + d1 * sq[c + 1];
                qp1 += d2 * sq[c] + d3 * sq[c + 1];
                kp0 += d0 * sk[c] + d1 * sk[c + 1];
                kp1 += d2 * sk[c] + d3 * sk[c + 1];
            }
            qp0 += __shfl_xor_sync(0xffffffffu, qp0, 1); qp0 += __shfl_xor_sync(0xffffffffu, qp0, 2);
            qp1 += __shfl_xor_sync(0xffffffffu, qp1, 1); qp1 += __shfl_xor_sync(0xffffffffu, qp1, 2);
            kp0 += __shfl_xor_sync(0xffffffffu, kp0, 1); kp0 += __shfl_xor_sync(0xffffffffu, kp0, 2);
            kp1 += __shfl_xor_sync(0xffffffffu, kp1, 1); kp1 += __shfl_xor_sync(0xffffffffu, kp1, 2);
            if (t == 0) {
                int n0 = base + rowbase + g, n1 = n0 + 8;
                if (n0 < n) { g_qv[n0 * 16 + r] = qp0; g_kv[n0 * 16 + r] = kp0; }
                if (n1 < n) { g_qv[n1 * 16 + r] = qp1; g_kv[n1 * 16 + r] = kp1; }
            }
        }
        __syncwarp();
        #pragma unroll
        for (int i = 0; i < 16; i++) {
            int rl = w * 32 + 2 * i + (lane >> 4);
            int node = base + rl;
            if (node < n) {
                uint32_t v = *(const uint32_t*)&xout[rl][(lane & 15) * 2];
                *(uint32_t*)&g_xr[((size_t)r * n + node) * 32 + (lane & 15) * 2] = v;
            }
        }
    }
}

// ONE-PASS edge kernel (R11 structure): float LN-stats reduction tail.
__global__ void k_edge(const float* __restrict__ bias, int layer, int n) {
    int warp = threadIdx.x >> 5, lane = threadIdx.x & 31;
    int node = blockIdx.x * 8 + warp;
    float h = 0.f;
    bool active = node < n;
    __shared__ float sh_qv[8][16];
    __shared__ float sh_h[8][32];
    if (active && lane < 16) sh_qv[warp][lane] = g_qv[node * 16 + lane];
    __syncwarp();
    if (active) {
        int beg = g_rowptr[node], end = g_rowptr[node + 1];
        float res = (layer > 0) ? g_x[(size_t)node * 32 + lane] : 0.f;
        if (end > beg) {
            int fq = lane & 3, eg = lane >> 2;
            float s = 0.f;
            float acc[8];
            #pragma unroll
            for (int j = 0; j < 8; j++) acc[j] = 0.f;
            for (int cb = beg; cb < end; cb += 32) {
                int i = cb + lane;
                float ee = 0.f;
                int ofs = 0;
                if (i < end) {
                    int p = g_epack[i];
                    int r = p >> 20, src = p & 0xFFFFF;
                    float a = sh_qv[warp][r] + g_kv[src * 16 + r];
                    a = (a > 0.f) ? a : 0.2f * a;
                    ee = __expf(a);
                    ofs = (r * n + src) * 32;
                }
                s += ee;
                int cnt = min(32, end - cb);
                for (int jb = 0; jb < cnt; jb += 8) {
                    int sl = jb + eg;
                    float pw = __shfl_sync(0xffffffffu, ee, sl & 31);
                    int of = __shfl_sync(0xffffffffu, ofs, sl & 31);
                    if (sl >= cnt) pw = 0.f;
                    uint4 v = *(const uint4*)&g_xr[(size_t)of + fq * 8];
                    float2 f0 = __half22float2(*(__half2*)&v.x);
                    float2 f1 = __half22float2(*(__half2*)&v.y);
                    float2 f2 = __half22float2(*(__half2*)&v.z);
                    float2 f3 = __half22float2(*(__half2*)&v.w);
                    acc[0] += pw * f0.x; acc[1] += pw * f0.y;
                    acc[2] += pw * f1.x; acc[3] += pw * f1.y;
                    acc[4] += pw * f2.x; acc[5] += pw * f2.y;
                    acc[6] += pw * f3.x; acc[7] += pw * f3.y;
                }
            }
            s = warpSumF(s);
            float inv = __fdividef(1.f, s + 1e-16f);
            #pragma unroll
            for (int j = 0; j < 8; j++) {
                acc[j] += __shfl_xor_sync(0xffffffffu, acc[j], 4);
                acc[j] += __shfl_xor_sync(0xffffffffu, acc[j], 8);
                acc[j] += __shfl_xor_sync(0xffffffffu, acc[j], 16);
            }
            if (eg == 0) {
                #pragma unroll
                for (int j = 0; j < 8; j++) sh_h[warp][fq * 8 + j] = acc[j] * inv;
            }
            __syncwarp();
            h = sh_h[warp][lane];
        }
        h += bias[lane] + res;
        g_h[(size_t)node * 32 + lane] = h;
    }
    // LN stats: float warp sums (32 O(1) values), double only at the atomic.
    float v = active ? h : 0.f;
    float v2 = active ? h * h : 0.f;
    v = warpSumF(v); v2 = warpSumF(v2);
    __shared__ float shs[2][8];
    if (lane == 0) { shs[0][warp] = v; shs[1][warp] = v2; }
    __syncthreads();
    if (threadIdx.x == 0) {
        double a = 0, b = 0;
        for (int ww = 0; ww < 8; ww++) { a += (double)shs[0][ww]; b += (double)shs[1][ww]; }
        atomicAdd(&g_stats[layer][0], a);
        atomicAdd(&g_stats[layer][1], b);
    }
}

__global__ void k_lnact(const float* __restrict__ lnw, const float* __restrict__ lnb,
                        int layer, int n, int dopool) {
    __shared__ float s_mu, s_std;
    __shared__ float sw[32], sb2[32];
    if (threadIdx.x == 0) {
        double cnt = (double)n * 32.0;
        double mu = g_stats[layer][0] / cnt;
        double var = g_stats[layer][1] / cnt - mu * mu;
        if (var < 0.0) var = 0.0;
        s_mu = (float)mu;
        s_std = (float)sqrt(var) + 1e-5f;
    }
    if (threadIdx.x < 32) { sw[threadIdx.x] = lnw[threadIdx.x]; sb2[threadIdx.x] = lnb[threadIdx.x]; }
    __syncthreads();
    float mu = s_mu, stdpe = s_std;
    if (!dopool) {
        // vectorized: 4 consecutive features per thread
        int total4 = n * 8;
        int fb = (threadIdx.x * 4) & 31;
        float w0 = sw[fb], w1 = sw[fb + 1], w2 = sw[fb + 2], w3 = sw[fb + 3];
        float b0 = sb2[fb], b1 = sb2[fb + 1], b2 = sb2[fb + 2], b3 = sb2[fb + 3];
        int stride = gridDim.x * blockDim.x;
        for (int i4 = blockIdx.x * blockDim.x + threadIdx.x; i4 < total4; i4 += stride) {
            float4 hv = *(const float4*)&g_h[(size_t)i4 * 4];
            float t0 = (hv.x - mu) / stdpe * w0 + b0;
            float t1 = (hv.y - mu) / stdpe * w1 + b1;
            float t2 = (hv.z - mu) / stdpe * w2 + b2;
            float t3 = (hv.w - mu) / stdpe * w3 + b3;
            float4 xv;
            xv.x = t0 / (1.f + __expf(-t0));
            xv.y = t1 / (1.f + __expf(-t1));
            xv.z = t2 / (1.f + __expf(-t2));
            xv.w = t3 / (1.f + __expf(-t3));
            *(float4*)&g_x[(size_t)i4 * 4] = xv;
        }
    } else {
        int f = threadIdx.x & 31;
        float w = sw[f], b = sb2[f];
        double acc = 0.0;
        int total = n * 32;
        for (int i = blockIdx.x * blockDim.x + threadIdx.x; i < total; i += gridDim.x * blockDim.x) {
            float t = (g_h[i] - mu) / stdpe * w + b;
            float sig = 1.f / (1.f + __expf(-t));
            float xo = t * sig;
            g_x[i] = xo;
            acc += (double)xo;
        }
        __shared__ double shd[8][32];
        int warp = threadIdx.x >> 5;
        shd[warp][f] = acc;
        __syncthreads();
        if (warp == 0) {
            double a = 0;
            for (int ww = 0; ww < 8; ww++) a += shd[ww][f];
            atomicAdd(&g_pool[f], a);
        }
    }
}

__global__ void k_final(const float* __restrict__ W, const float* __restrict__ b,
                        float* __restrict__ out, int n) {
    __shared__ float x3[32];
    if (threadIdx.x < 32) x3[threadIdx.x] = (float)(g_pool[threadIdx.x] / (double)n);
    __syncthreads();
    int j = threadIdx.x;
    if (j < 256) {
        float acc = b[j];
        #pragma unroll
        for (int o = 0; o < 32; o++) acc += x3[o] * W[j * 32 + o];
        float sig = 1.f / (1.f + expf(-acc));
        out[j] = acc * sig;
    }
}

extern "C" void kernel_launch(void* const* d_in, const int* in_sizes, int n_in,
                              void* d_out, int out_size) {
    const float* db1  = (const float*)d_in[0];
    const int*   ei   = (const int*)d_in[2];
    const int*   et   = (const int*)d_in[3];
    const float* W0   = (const float*)d_in[6];
    const float* q0   = (const float*)d_in[7];
    const float* k0   = (const float*)d_in[8];
    const float* b0   = (const float*)d_in[9];
    const float* Ws   = (const float*)d_in[10];
    const float* qs   = (const float*)d_in[11];
    const float* ks   = (const float*)d_in[12];
    const float* bs   = (const float*)d_in[13];
    const float* lnw  = (const float*)d_in[14];
    const float* lnb  = (const float*)d_in[15];
    const float* ln1w = (const float*)d_in[16];
    const float* ln1b = (const float*)d_in[17];
    const float* l1W  = (const float*)d_in[18];
    const float* l1b  = (const float*)d_in[19];
    float* out = (float*)d_out;
    int n = in_sizes[0] / 35;
    int e = in_sizes[3];
    int ntot = n * 16;
    int nb16 = (ntot + 255) / 256;

    k_zero<<<512, 256>>>();
    k_stats<<<512, 256>>>(db1, n);
    k_eigh<<<1, 1>>>(n);
    k_buildx0<<<(n * 36 + 255) / 256, 256>>>(db1, ln1w, ln1b, n);

    k_hist<<<(e + 255) / 256, 256>>>(ei, et, e);
    k_scanA<<<nb16, 256>>>(ntot);
    k_scanB<<<1, 512>>>(nb16);
    k_scanC<<<nb16, 256>>>(ntot, n, e);
    k_scatter<<<(e + 255) / 256, 256>>>(ei, et, e);

    int gg = (n + 127) / 128;
    for (int l = 0; l < NLAY; l++) {
        const float* bias = (l == 0) ? b0 : bs + (l - 1) * 32;
        if (l == 0) {
            k_gemm<35, 36, 48><<<gg, 128>>>(W0, q0, k0, n);
        } else {
            k_gemm<32, 32, 32><<<gg, 128>>>(Ws + (size_t)(l - 1) * RREL * 32 * 32,
                                            qs + (l - 1) * 32, ks + (l - 1) * 32, n);
        }
        k_edge<<<(n + 7) / 8, 256>>>(bias, l, n);
        k_lnact<<<512, 256>>>(lnw + l * 32, lnb + l * 32, l, n, (l == NLAY - 1) ? 1 : 0);
    }
    k_final<<<1, 256>>>(l1W, l1b, out, n);
}